// round 8
// baseline (speedup 1.0000x reference)
#include <cuda_runtime.h>
#include <cuda_bf16.h>
#include <cuda_fp16.h>
#include <math.h>
#include <stdint.h>
#include <string.h>

// ---------------------------------------------------------------------------
// Problem constants
// ---------------------------------------------------------------------------
#define M_ROWS 4096
#define K_DIM  1024
#define N_DIM  1024
#define HEADS  16
#define DHEAD  64
#define TSEQ   1024
#define BATCH  4

// fp16 2-product widened K for projections: A' = [xh|xh], B' = [Whi|Wlo]
#define KP2    2048

// fp32 scratch (attention inputs)
__device__ float g_Q[M_ROWS * K_DIM];
__device__ float g_K[M_ROWS * K_DIM];
__device__ float g_V[M_ROWS * K_DIM];

// fp16 scratch for projection GEMMs
__device__ __align__(16) __half g_xs[M_ROWS * KP2];
__device__ __align__(16) __half g_As[M_ROWS * KP2];
__device__ __align__(16) __half g_Ws[4 * N_DIM * KP2];

// attention fp16 operands
// Q' per head: [t=1024][128] = [Qh|Qh];  K' per head: [t=1024][128] = [Khi|Klo]
// Vt per head: [d=64][t=1024] hi and lo
__device__ __align__(16) __half g_Qs2[64 * 1024 * 128];
__device__ __align__(16) __half g_Ks2[64 * 1024 * 128];
__device__ __align__(16) __half g_Vthi[64 * 64 * 1024];
__device__ __align__(16) __half g_Vtlo[64 * 64 * 1024];

// ---------------------------------------------------------------------------
// PTX helpers
// ---------------------------------------------------------------------------
__device__ __forceinline__ uint32_t smem_u32(const void* p) {
    uint32_t a;
    asm("{ .reg .u64 t; cvta.to.shared.u64 t, %1; cvt.u32.u64 %0, t; }"
        : "=r"(a) : "l"(p));
    return a;
}
__device__ __forceinline__ void cp16(uint32_t s, const void* g) {
    asm volatile("cp.async.cg.shared.global [%0], [%1], 16;" :: "r"(s), "l"(g));
}
#define CP_COMMIT() asm volatile("cp.async.commit_group;" ::: "memory")
#define CP_WAIT(n)  asm volatile("cp.async.wait_group %0;" :: "n"(n) : "memory")

#define LDSM_X4(r, addr)                                                       \
    asm volatile("ldmatrix.sync.aligned.m8n8.x4.shared.b16 {%0,%1,%2,%3}, [%4];" \
                 : "=r"((r)[0]), "=r"((r)[1]), "=r"((r)[2]), "=r"((r)[3])      \
                 : "r"(addr))

__device__ __forceinline__ void mma16816h(float* c, const uint32_t* a,
                                          const uint32_t* b) {
    asm volatile(
        "mma.sync.aligned.m16n8k16.row.col.f32.f16.f16.f32 "
        "{%0,%1,%2,%3}, {%4,%5,%6,%7}, {%8,%9}, {%0,%1,%2,%3};"
        : "+f"(c[0]), "+f"(c[1]), "+f"(c[2]), "+f"(c[3])
        : "r"(a[0]), "r"(a[1]), "r"(a[2]), "r"(a[3]), "r"(b[0]), "r"(b[1]));
}

__device__ __forceinline__ uint32_t packh2(float x, float y) {
    __half2 t = __floats2half2_rn(x, y);
    uint32_t u;
    memcpy(&u, &t, 4);
    return u;
}

// ---------------------------------------------------------------------------
// HMMA fp16 NT GEMM (round-7 validated, unchanged)
// ---------------------------------------------------------------------------
#define GBM 128
#define GBN 128
#define GBK 64
#define TILE_B  (128 * 128)
#define STAGE_B (2 * TILE_B)
#define NSTAGE  3
#define NCH     (KP2 / GBK)              // 32
#define GEMM_SMEM (NSTAGE * STAGE_B)     // 98304

__device__ __forceinline__ uint32_t swz(uint32_t row, uint32_t seg) {
    return row * 128 + ((seg ^ (row & 7)) * 16);
}

__device__ __forceinline__ void load_chunk(const __half* __restrict__ A,
                                           const __half* __restrict__ B,
                                           int bm, int bn, int k0,
                                           uint32_t sA, uint32_t sB) {
    const int tid = threadIdx.x;
    const int row = tid >> 1;
    const int sb  = (tid & 1) * 4;
#pragma unroll
    for (int j = 0; j < 4; j++) {
        const int seg = sb + j;
        cp16(sA + swz(row, seg), A + (size_t)(bm + row) * KP2 + k0 + seg * 8);
        cp16(sB + swz(row, seg), B + (size_t)(bn + row) * KP2 + k0 + seg * 8);
    }
    CP_COMMIT();
}

__device__ void gemm_hmma_body(const __half* __restrict__ A,
                               const __half* __restrict__ B,
                               const float* __restrict__ bias,
                               float* __restrict__ C) {
    extern __shared__ char sm[];
    const uint32_t smb = smem_u32(sm);

    const int tid  = threadIdx.x;
    const int wid  = tid >> 5;
    const int lane = tid & 31;
    const int wm   = wid >> 2;
    const int wn   = wid & 3;
    const int bm   = blockIdx.y * GBM;
    const int bn   = blockIdx.x * GBN;

    float acc[4][4][4];
#pragma unroll
    for (int i = 0; i < 4; i++)
#pragma unroll
        for (int j = 0; j < 4; j++)
#pragma unroll
            for (int r = 0; r < 4; r++) acc[i][j][r] = 0.f;

#pragma unroll
    for (int s = 0; s < NSTAGE; s++)
        load_chunk(A, B, bm, bn, s * GBK,
                   smb + s * STAGE_B, smb + s * STAGE_B + TILE_B);

    for (int c = 0; c < NCH; c++) {
        const int rem = NCH - 1 - c;
        if (rem >= 2)      CP_WAIT(2);
        else if (rem == 1) CP_WAIT(1);
        else               CP_WAIT(0);
        __syncthreads();

        const uint32_t aB = smb + (c % NSTAGE) * STAGE_B;
        const uint32_t bB = aB + TILE_B;

#pragma unroll
        for (int ks = 0; ks < 4; ks++) {
            uint32_t afr[4][4];
#pragma unroll
            for (int mi = 0; mi < 4; mi++) {
                const int row = wm * 64 + mi * 16 + (lane & 15);
                const int seg = ks * 2 + (lane >> 4);
                LDSM_X4(afr[mi], aB + swz(row, seg));
            }
            uint32_t bfr[2][4];
            const int g = lane >> 3;
#pragma unroll
            for (int np = 0; np < 2; np++) {
                const int row = wn * 32 + np * 16 + (g >> 1) * 8 + (lane & 7);
                const int seg = ks * 2 + (g & 1);
                LDSM_X4(bfr[np], bB + swz(row, seg));
            }
#pragma unroll
            for (int mi = 0; mi < 4; mi++) {
#pragma unroll
                for (int ni = 0; ni < 4; ni++)
                    mma16816h(acc[mi][ni], afr[mi], &bfr[ni >> 1][(ni & 1) * 2]);
            }
        }
        __syncthreads();

        if (c + NSTAGE < NCH)
            load_chunk(A, B, bm, bn, (c + NSTAGE) * GBK,
                       smb + (c % NSTAGE) * STAGE_B,
                       smb + (c % NSTAGE) * STAGE_B + TILE_B);
    }

#pragma unroll
    for (int mi = 0; mi < 4; mi++) {
#pragma unroll
        for (int ni = 0; ni < 4; ni++) {
            const int r0 = bm + wm * 64 + mi * 16 + (lane >> 2);
            const int c0 = bn + wn * 32 + ni * 8 + (lane & 3) * 2;
            float2 v0 = make_float2(acc[mi][ni][0], acc[mi][ni][1]);
            float2 v1 = make_float2(acc[mi][ni][2], acc[mi][ni][3]);
            if (bias) {
                const float b0 = bias[c0], b1 = bias[c0 + 1];
                v0.x += b0; v0.y += b1;
                v1.x += b0; v1.y += b1;
            }
            *(float2*)&C[(size_t)r0 * N_DIM + c0]       = v0;
            *(float2*)&C[(size_t)(r0 + 8) * N_DIM + c0] = v1;
        }
    }
}

__global__ __launch_bounds__(256, 2) void qkv_hmma_kernel() {
    const int z = blockIdx.z;
    float* C = (z == 0) ? g_Q : (z == 1) ? g_K : g_V;
    gemm_hmma_body(g_xs, g_Ws + (size_t)z * N_DIM * KP2, nullptr, C);
}

__global__ __launch_bounds__(256, 2) void out_hmma_kernel(const float* __restrict__ bo,
                                                          float* __restrict__ out) {
    gemm_hmma_body(g_As, g_Ws + (size_t)3 * N_DIM * KP2, bo, out);
}

// ---------------------------------------------------------------------------
// conversions
// ---------------------------------------------------------------------------
// x -> fp16 A' = [xh | xh]
__global__ void conv_x_kernel(const float* __restrict__ src) {
    const int i = blockIdx.x * blockDim.x + threadIdx.x;
    if (i >= M_ROWS * K_DIM / 4) return;
    const int r = i / (K_DIM / 4);
    const int k4 = (i % (K_DIM / 4)) * 4;
    float4 v = ((const float4*)src)[i];
    const __half2 h0 = __floats2half2_rn(v.x, v.y);
    const __half2 h1 = __floats2half2_rn(v.z, v.w);
    __half2* d0 = (__half2*)(g_xs + (size_t)r * KP2 + k4);
    __half2* d1 = (__half2*)(g_xs + (size_t)r * KP2 + 1024 + k4);
    d0[0] = h0; d0[1] = h1;
    d1[0] = h0; d1[1] = h1;
}

// W -> fp16 B' = [Whi | Wlo]
__global__ void conv_w_kernel(const float* __restrict__ Wq, const float* __restrict__ Wk,
                              const float* __restrict__ Wv, const float* __restrict__ Wo) {
    const int z = blockIdx.z;
    const float* src = (z == 0) ? Wq : (z == 1) ? Wk : (z == 2) ? Wv : Wo;
    const int i = blockIdx.x * blockDim.x + threadIdx.x;
    if (i >= N_DIM * K_DIM / 4) return;
    const int n = i / (K_DIM / 4);
    const int k4 = (i % (K_DIM / 4)) * 4;
    float4 v = ((const float4*)src)[i];
    const __half hx = __float2half_rn(v.x);
    const __half hy = __float2half_rn(v.y);
    const __half hz = __float2half_rn(v.z);
    const __half hw = __float2half_rn(v.w);
    __half* dst = g_Ws + (size_t)z * N_DIM * KP2;
    __half2* d0 = (__half2*)(dst + (size_t)n * KP2 + k4);
    __half2* d1 = (__half2*)(dst + (size_t)n * KP2 + 1024 + k4);
    d0[0] = __half2(hx, hy);
    d0[1] = __half2(hz, hw);
    d1[0] = __half2(__float2half_rn(v.x - __half2float(hx)),
                    __float2half_rn(v.y - __half2float(hy)));
    d1[1] = __half2(__float2half_rn(v.z - __half2float(hz)),
                    __float2half_rn(v.w - __half2float(hw)));
}

// Q'[bh][t][128] = [Qh|Qh],  K'[bh][t][128] = [Khi|Klo]  (fp16)
__global__ void conv_qk_kernel() {
    const int i = blockIdx.x * blockDim.x + threadIdx.x;
    if (i >= M_ROWS * 256) return;
    const int row = i >> 8;
    const int e4  = i & 255;
    const int h   = e4 >> 4;
    const int dd  = (e4 & 15) * 4;
    const int b   = row >> 10, t = row & 1023;
    const size_t base = ((size_t)((b * 16 + h) * 1024) + t) * 128;

    float4 q = *(const float4*)&g_Q[(size_t)row * K_DIM + h * 64 + dd];
    float4 k = *(const float4*)&g_K[(size_t)row * K_DIM + h * 64 + dd];

    const __half2 qh0 = __floats2half2_rn(q.x, q.y);
    const __half2 qh1 = __floats2half2_rn(q.z, q.w);
    const __half kx = __float2half_rn(k.x);
    const __half ky = __float2half_rn(k.y);
    const __half kz = __float2half_rn(k.z);
    const __half kw = __float2half_rn(k.w);

    __half2* p;
    p = (__half2*)(g_Qs2 + base + dd);       p[0] = qh0; p[1] = qh1;
    p = (__half2*)(g_Qs2 + base + 64 + dd);  p[0] = qh0; p[1] = qh1;

    p = (__half2*)(g_Ks2 + base + dd);
    p[0] = __half2(kx, ky);
    p[1] = __half2(kz, kw);
    p = (__half2*)(g_Ks2 + base + 64 + dd);
    p[0] = __half2(__float2half_rn(k.x - __half2float(kx)),
                   __float2half_rn(k.y - __half2float(ky)));
    p[1] = __half2(__float2half_rn(k.z - __half2float(kz)),
                   __float2half_rn(k.w - __half2float(kw)));
}

// Vt[bh][d][t] hi/lo fp16 — transposed per head via smem tile
__global__ void conv_vt_kernel() {
    __shared__ float vs[64][68];
    const int blk = blockIdx.x;
    const int bh = blk >> 4, tt = blk & 15;
    const int b = bh >> 4, h = bh & 15;
    const int t0 = tt * 64;
    const int tid = threadIdx.x;

    const int r  = tid >> 4;
    const int c4 = (tid & 15) * 4;
#pragma unroll
    for (int j = 0; j < 4; j++) {
        const int t = r + j * 16;
        float4 v = *(const float4*)&g_V[(size_t)(b * 1024 + t0 + t) * K_DIM + h * 64 + c4];
        vs[t][c4 + 0] = v.x; vs[t][c4 + 1] = v.y;
        vs[t][c4 + 2] = v.z; vs[t][c4 + 3] = v.w;
    }
    __syncthreads();

    const int d  = tid >> 2;
    const int ts = (tid & 3) * 16;
    const size_t obase = ((size_t)bh * 64 + d) * 1024 + t0 + ts;
#pragma unroll
    for (int j = 0; j < 16; j += 2) {
        const float v0 = vs[ts + j][d];
        const float v1 = vs[ts + j + 1][d];
        const __half h0 = __float2half_rn(v0);
        const __half h1 = __float2half_rn(v1);
        *(__half2*)&g_Vthi[obase + j] = __half2(h0, h1);
        *(__half2*)&g_Vtlo[obase + j] =
            __half2(__float2half_rn(v0 - __half2float(h0)),
                    __float2half_rn(v1 - __half2float(h1)));
    }
}

// ---------------------------------------------------------------------------
// HMMA flash attention, fp16 2-product:
//   S = Qh·Khi + Qh·Klo  (K'=128, 8 k-steps)
//   O += Ph·Vhi + Ph·Vlo (P packed fp16, no residual)
// Epilogue writes fp16 A' = [Ah|Ah].
// Smem pitches 136 fp16 -> conflict-free ldmatrix.
// ---------------------------------------------------------------------------
#define QLD 136
#define VLD 136
#define ATTN_SMEM ((2 * 128 * QLD + 2 * 64 * VLD) * 2)   // 104448

__global__ __launch_bounds__(256) void attn_hmma_kernel()
{
    extern __shared__ char sm[];
    const uint32_t smb = smem_u32(sm);
    const uint32_t sQ  = smb;
    const uint32_t sK  = smb + 128 * QLD * 2;
    const uint32_t sVh = smb + 2 * 128 * QLD * 2;
    const uint32_t sVl = sVh + 64 * VLD * 2;

    const int tid  = threadIdx.x;
    const int wid  = tid >> 5;
    const int lane = tid & 31;
    const int g    = lane >> 2;
    const int qt   = blockIdx.x;
    const int bh   = blockIdx.y;
    const int b    = bh >> 4;
    const int h    = bh & 15;
    const int cbase = h * DHEAD;
    const int qrow0 = b * TSEQ + qt * 128;

    // load Q' tile (128 x 128 fp16) once
    for (int i = tid; i < 128 * 16; i += 256) {
        const int r = i >> 4, s = i & 15;
        cp16(sQ + (r * QLD + s * 8) * 2,
             g_Qs2 + ((size_t)bh * 1024 + qt * 128 + r) * 128 + s * 8);
    }
    CP_COMMIT();

    float acc_o[8][4];
#pragma unroll
    for (int i = 0; i < 8; i++)
#pragma unroll
        for (int r = 0; r < 4; r++) acc_o[i][r] = 0.f;
    float m0 = -INFINITY, m1 = -INFINITY, l0 = 0.f, l1 = 0.f;

    for (int kt = 0; kt < 8; kt++) {
        __syncthreads();
        for (int i = tid; i < 128 * 16; i += 256) {
            const int r = i >> 4, s = i & 15;
            cp16(sK + (r * QLD + s * 8) * 2,
                 g_Ks2 + ((size_t)bh * 1024 + kt * 128 + r) * 128 + s * 8);
        }
        for (int i = tid; i < 64 * 16; i += 256) {
            const int r = i >> 4, s = i & 15;
            cp16(sVh + (r * VLD + s * 8) * 2,
                 g_Vthi + ((size_t)bh * 64 + r) * 1024 + kt * 128 + s * 8);
            cp16(sVl + (r * VLD + s * 8) * 2,
                 g_Vtlo + ((size_t)bh * 64 + r) * 1024 + kt * 128 + s * 8);
        }
        CP_COMMIT();
        CP_WAIT(0);
        __syncthreads();

        // ---- S = Q' K'^T : 8 k-steps ----
        float s_acc[16][4];
#pragma unroll
        for (int ni = 0; ni < 16; ni++)
#pragma unroll
            for (int r = 0; r < 4; r++) s_acc[ni][r] = 0.f;

#pragma unroll
        for (int ks = 0; ks < 8; ks++) {
            uint32_t a[4];
            LDSM_X4(a, sQ + ((wid * 16 + (lane & 15)) * QLD + ks * 16 + (lane >> 4) * 8) * 2);
            uint32_t bf[8][4];
            const int gg = lane >> 3;
#pragma unroll
            for (int np = 0; np < 8; np++) {
                const int row = np * 16 + (gg >> 1) * 8 + (lane & 7);
                LDSM_X4(bf[np], sK + (row * QLD + ks * 16 + (gg & 1) * 8) * 2);
            }
#pragma unroll
            for (int ni = 0; ni < 16; ni++)
                mma16816h(s_acc[ni], a, &bf[ni >> 1][(ni & 1) * 2]);
        }

        // ---- online softmax ----
        float rm0 = -INFINITY, rm1 = -INFINITY;
#pragma unroll
        for (int ni = 0; ni < 16; ni++) {
            s_acc[ni][0] *= 0.125f; s_acc[ni][1] *= 0.125f;
            s_acc[ni][2] *= 0.125f; s_acc[ni][3] *= 0.125f;
            rm0 = fmaxf(rm0, fmaxf(s_acc[ni][0], s_acc[ni][1]));
            rm1 = fmaxf(rm1, fmaxf(s_acc[ni][2], s_acc[ni][3]));
        }
        rm0 = fmaxf(rm0, __shfl_xor_sync(0xffffffffu, rm0, 1));
        rm0 = fmaxf(rm0, __shfl_xor_sync(0xffffffffu, rm0, 2));
        rm1 = fmaxf(rm1, __shfl_xor_sync(0xffffffffu, rm1, 1));
        rm1 = fmaxf(rm1, __shfl_xor_sync(0xffffffffu, rm1, 2));

        const float nm0 = fmaxf(m0, rm0);
        const float nm1 = fmaxf(m1, rm1);
        const float a0 = __expf(m0 - nm0);
        const float a1 = __expf(m1 - nm1);

        float rs0 = 0.f, rs1 = 0.f;
#pragma unroll
        for (int ni = 0; ni < 16; ni++) {
            s_acc[ni][0] = __expf(s_acc[ni][0] - nm0);
            s_acc[ni][1] = __expf(s_acc[ni][1] - nm0);
            s_acc[ni][2] = __expf(s_acc[ni][2] - nm1);
            s_acc[ni][3] = __expf(s_acc[ni][3] - nm1);
            rs0 += s_acc[ni][0] + s_acc[ni][1];
            rs1 += s_acc[ni][2] + s_acc[ni][3];
        }
        rs0 += __shfl_xor_sync(0xffffffffu, rs0, 1);
        rs0 += __shfl_xor_sync(0xffffffffu, rs0, 2);
        rs1 += __shfl_xor_sync(0xffffffffu, rs1, 1);
        rs1 += __shfl_xor_sync(0xffffffffu, rs1, 2);

        l0 = l0 * a0 + rs0;  m0 = nm0;
        l1 = l1 * a1 + rs1;  m1 = nm1;

#pragma unroll
        for (int ni = 0; ni < 8; ni++) {
            acc_o[ni][0] *= a0; acc_o[ni][1] *= a0;
            acc_o[ni][2] *= a1; acc_o[ni][3] *= a1;
        }

        // ---- O += P V (P fp16, V hi+lo) ----
        const int gg = lane >> 3;
#pragma unroll
        for (int ks = 0; ks < 8; ks++) {
            uint32_t ph[4];
            {
                const float* t0 = s_acc[2 * ks];
                const float* t1 = s_acc[2 * ks + 1];
                ph[0] = packh2(t0[0], t0[1]);
                ph[1] = packh2(t0[2], t0[3]);
                ph[2] = packh2(t1[0], t1[1]);
                ph[3] = packh2(t1[2], t1[3]);
            }
            uint32_t vh[4][4], vl[4][4];
#pragma unroll
            for (int np = 0; np < 4; np++) {
                const int row = np * 16 + (gg >> 1) * 8 + (lane & 7);
                const int col = ks * 16 + (gg & 1) * 8;
                LDSM_X4(vh[np], sVh + (row * VLD + col) * 2);
                LDSM_X4(vl[np], sVl + (row * VLD + col) * 2);
            }
#pragma unroll
            for (int ni = 0; ni < 8; ni++) {
                mma16816h(acc_o[ni], ph, &vh[ni >> 1][(ni & 1) * 2]);
                mma16816h(acc_o[ni], ph, &vl[ni >> 1][(ni & 1) * 2]);
            }
        }
    }

    // ---- normalize and write fp16 A' = [Ah | Ah] ----
    const float inv0 = 1.0f / l0;
    const float inv1 = 1.0f / l1;
    const int row0 = qrow0 + wid * 16 + g;
#pragma unroll
    for (int ni = 0; ni < 8; ni++) {
        const int col = cbase + ni * 8 + (lane & 3) * 2;
        {
            const __half2 hv = __floats2half2_rn(acc_o[ni][0] * inv0,
                                                 acc_o[ni][1] * inv0);
            __half* rp = g_As + (size_t)row0 * KP2;
            *(__half2*)(rp + col)        = hv;
            *(__half2*)(rp + 1024 + col) = hv;
        }
        {
            const __half2 hv = __floats2half2_rn(acc_o[ni][2] * inv1,
                                                 acc_o[ni][3] * inv1);
            __half* rp = g_As + (size_t)(row0 + 8) * KP2;
            *(__half2*)(rp + col)        = hv;
            *(__half2*)(rp + 1024 + col) = hv;
        }
    }
}

// ---------------------------------------------------------------------------
// kernel_launch
// ---------------------------------------------------------------------------
extern "C" void kernel_launch(void* const* d_in, const int* in_sizes, int n_in,
                              void* d_out, int out_size)
{
    const float* x  = (const float*)d_in[0];
    const float* Wq = (const float*)d_in[1];
    const float* Wk = (const float*)d_in[2];
    const float* Wv = (const float*)d_in[3];
    const float* Wo = (const float*)d_in[4];
    const float* bo = (const float*)d_in[5];
    float* out = (float*)d_out;

    cudaFuncSetAttribute(qkv_hmma_kernel, cudaFuncAttributeMaxDynamicSharedMemorySize, GEMM_SMEM);
    cudaFuncSetAttribute(out_hmma_kernel, cudaFuncAttributeMaxDynamicSharedMemorySize, GEMM_SMEM);
    cudaFuncSetAttribute(attn_hmma_kernel, cudaFuncAttributeMaxDynamicSharedMemorySize, ATTN_SMEM);

    // 1) conversions for projections (fp16 2-product)
    {
        const int nx = M_ROWS * K_DIM / 4;
        conv_x_kernel<<<(nx + 255) / 256, 256>>>(x);
        const int nw = N_DIM * K_DIM / 4;
        conv_w_kernel<<<dim3((nw + 255) / 256, 1, 4), 256>>>(Wq, Wk, Wv, Wo);
    }

    // 2) QKV projections (fp16 HMMA)
    qkv_hmma_kernel<<<dim3(N_DIM / GBN, M_ROWS / GBM, 3), 256, GEMM_SMEM>>>();

    // 3) attention operand conversions (fp16 2-product)
    conv_qk_kernel<<<(M_ROWS * 256) / 256, 256>>>();
    conv_vt_kernel<<<64 * 16, 256>>>();

    // 4) attention (fp16 2-product HMMA flash; writes fp16 g_As)
    attn_hmma_kernel<<<dim3(8, 64), 256, ATTN_SMEM>>>();

    // 5) output projection + bias (fp16 HMMA)
    out_hmma_kernel<<<dim3(N_DIM / GBN, M_ROWS / GBM), 256, GEMM_SMEM>>>(bo, out);
}

// round 9
// speedup vs baseline: 1.7467x; 1.7467x over previous
#include <cuda_runtime.h>
#include <cuda_bf16.h>
#include <cuda_fp16.h>
#include <math.h>
#include <stdint.h>
#include <string.h>

// ---------------------------------------------------------------------------
// Problem constants
// ---------------------------------------------------------------------------
#define M_ROWS 4096
#define K_DIM  1024
#define N_DIM  1024
#define HEADS  16
#define DHEAD  64
#define TSEQ   1024
#define BATCH  4

// fp32 scratch (attention inputs)
__device__ float g_Q[M_ROWS * K_DIM];
__device__ float g_K[M_ROWS * K_DIM];
__device__ float g_V[M_ROWS * K_DIM];

// fp16 scratch for projection GEMMs (single-product: K = 1024)
__device__ __align__(16) __half g_xs[M_ROWS * K_DIM];
__device__ __align__(16) __half g_As[M_ROWS * K_DIM];
__device__ __align__(16) __half g_Ws[4 * N_DIM * K_DIM];

// attention split operands (bf16 3-product, round-7 validated layouts)
// Q' per head: [t=1024][192] = [hi|hi|lo];  K' per head: [t=1024][192] = [hi|lo|hi]
// Vt per head: [d=64][t=1024] hi and lo
__device__ __align__(16) __nv_bfloat16 g_Qs2[64 * 1024 * 192];
__device__ __align__(16) __nv_bfloat16 g_Ks2[64 * 1024 * 192];
__device__ __align__(16) __nv_bfloat16 g_Vthi[64 * 64 * 1024];
__device__ __align__(16) __nv_bfloat16 g_Vtlo[64 * 64 * 1024];

// ---------------------------------------------------------------------------
// PTX helpers
// ---------------------------------------------------------------------------
__device__ __forceinline__ uint32_t smem_u32(const void* p) {
    uint32_t a;
    asm("{ .reg .u64 t; cvta.to.shared.u64 t, %1; cvt.u32.u64 %0, t; }"
        : "=r"(a) : "l"(p));
    return a;
}
__device__ __forceinline__ void cp16(uint32_t s, const void* g) {
    asm volatile("cp.async.cg.shared.global [%0], [%1], 16;" :: "r"(s), "l"(g));
}
#define CP_COMMIT() asm volatile("cp.async.commit_group;" ::: "memory")
#define CP_WAIT(n)  asm volatile("cp.async.wait_group %0;" :: "n"(n) : "memory")

#define LDSM_X4(r, addr)                                                       \
    asm volatile("ldmatrix.sync.aligned.m8n8.x4.shared.b16 {%0,%1,%2,%3}, [%4];" \
                 : "=r"((r)[0]), "=r"((r)[1]), "=r"((r)[2]), "=r"((r)[3])      \
                 : "r"(addr))

__device__ __forceinline__ void mma16816h(float* c, const uint32_t* a,
                                          const uint32_t* b) {
    asm volatile(
        "mma.sync.aligned.m16n8k16.row.col.f32.f16.f16.f32 "
        "{%0,%1,%2,%3}, {%4,%5,%6,%7}, {%8,%9}, {%0,%1,%2,%3};"
        : "+f"(c[0]), "+f"(c[1]), "+f"(c[2]), "+f"(c[3])
        : "r"(a[0]), "r"(a[1]), "r"(a[2]), "r"(a[3]), "r"(b[0]), "r"(b[1]));
}
__device__ __forceinline__ void mma16816bf(float* c, const uint32_t* a,
                                           const uint32_t* b) {
    asm volatile(
        "mma.sync.aligned.m16n8k16.row.col.f32.bf16.bf16.f32 "
        "{%0,%1,%2,%3}, {%4,%5,%6,%7}, {%8,%9}, {%0,%1,%2,%3};"
        : "+f"(c[0]), "+f"(c[1]), "+f"(c[2]), "+f"(c[3])
        : "r"(a[0]), "r"(a[1]), "r"(a[2]), "r"(a[3]), "r"(b[0]), "r"(b[1]));
}

__device__ __forceinline__ uint32_t packbf2(float x, float y) {
    __nv_bfloat162 t = __floats2bfloat162_rn(x, y);
    uint32_t u;
    memcpy(&u, &t, 4);
    return u;
}

// ---------------------------------------------------------------------------
// HMMA fp16 NT GEMM: C[M,N] = A[M,1024] @ B[N,1024]^T (+ bias)
// CTA 128x128, BK=64, 3-stage cp.async, swizzled smem, 2 CTAs/SM.
// (round-6/7 validated structure; K halved to 1024)
// ---------------------------------------------------------------------------
#define GBM 128
#define GBN 128
#define GBK 64
#define TILE_B  (128 * 128)
#define STAGE_B (2 * TILE_B)
#define NSTAGE  3
#define NCH     (K_DIM / GBK)            // 16
#define GEMM_SMEM (NSTAGE * STAGE_B)     // 98304

__device__ __forceinline__ uint32_t swz(uint32_t row, uint32_t seg) {
    return row * 128 + ((seg ^ (row & 7)) * 16);
}

__device__ __forceinline__ void load_chunk(const __half* __restrict__ A,
                                           const __half* __restrict__ B,
                                           int bm, int bn, int k0,
                                           uint32_t sA, uint32_t sB) {
    const int tid = threadIdx.x;
    const int row = tid >> 1;
    const int sb  = (tid & 1) * 4;
#pragma unroll
    for (int j = 0; j < 4; j++) {
        const int seg = sb + j;
        cp16(sA + swz(row, seg), A + (size_t)(bm + row) * K_DIM + k0 + seg * 8);
        cp16(sB + swz(row, seg), B + (size_t)(bn + row) * K_DIM + k0 + seg * 8);
    }
    CP_COMMIT();
}

__device__ void gemm_hmma_body(const __half* __restrict__ A,
                               const __half* __restrict__ B,
                               const float* __restrict__ bias,
                               float* __restrict__ C) {
    extern __shared__ char sm[];
    const uint32_t smb = smem_u32(sm);

    const int tid  = threadIdx.x;
    const int wid  = tid >> 5;
    const int lane = tid & 31;
    const int wm   = wid >> 2;
    const int wn   = wid & 3;
    const int bm   = blockIdx.y * GBM;
    const int bn   = blockIdx.x * GBN;

    float acc[4][4][4];
#pragma unroll
    for (int i = 0; i < 4; i++)
#pragma unroll
        for (int j = 0; j < 4; j++)
#pragma unroll
            for (int r = 0; r < 4; r++) acc[i][j][r] = 0.f;

#pragma unroll
    for (int s = 0; s < NSTAGE; s++)
        load_chunk(A, B, bm, bn, s * GBK,
                   smb + s * STAGE_B, smb + s * STAGE_B + TILE_B);

    for (int c = 0; c < NCH; c++) {
        const int rem = NCH - 1 - c;
        if (rem >= 2)      CP_WAIT(2);
        else if (rem == 1) CP_WAIT(1);
        else               CP_WAIT(0);
        __syncthreads();

        const uint32_t aB = smb + (c % NSTAGE) * STAGE_B;
        const uint32_t bB = aB + TILE_B;

#pragma unroll
        for (int ks = 0; ks < 4; ks++) {
            uint32_t afr[4][4];
#pragma unroll
            for (int mi = 0; mi < 4; mi++) {
                const int row = wm * 64 + mi * 16 + (lane & 15);
                const int seg = ks * 2 + (lane >> 4);
                LDSM_X4(afr[mi], aB + swz(row, seg));
            }
            uint32_t bfr[2][4];
            const int g = lane >> 3;
#pragma unroll
            for (int np = 0; np < 2; np++) {
                const int row = wn * 32 + np * 16 + (g >> 1) * 8 + (lane & 7);
                const int seg = ks * 2 + (g & 1);
                LDSM_X4(bfr[np], bB + swz(row, seg));
            }
#pragma unroll
            for (int mi = 0; mi < 4; mi++) {
#pragma unroll
                for (int ni = 0; ni < 4; ni++)
                    mma16816h(acc[mi][ni], afr[mi], &bfr[ni >> 1][(ni & 1) * 2]);
            }
        }
        __syncthreads();

        if (c + NSTAGE < NCH)
            load_chunk(A, B, bm, bn, (c + NSTAGE) * GBK,
                       smb + (c % NSTAGE) * STAGE_B,
                       smb + (c % NSTAGE) * STAGE_B + TILE_B);
    }

#pragma unroll
    for (int mi = 0; mi < 4; mi++) {
#pragma unroll
        for (int ni = 0; ni < 4; ni++) {
            const int r0 = bm + wm * 64 + mi * 16 + (lane >> 2);
            const int c0 = bn + wn * 32 + ni * 8 + (lane & 3) * 2;
            float2 v0 = make_float2(acc[mi][ni][0], acc[mi][ni][1]);
            float2 v1 = make_float2(acc[mi][ni][2], acc[mi][ni][3]);
            if (bias) {
                const float b0 = bias[c0], b1 = bias[c0 + 1];
                v0.x += b0; v0.y += b1;
                v1.x += b0; v1.y += b1;
            }
            *(float2*)&C[(size_t)r0 * N_DIM + c0]       = v0;
            *(float2*)&C[(size_t)(r0 + 8) * N_DIM + c0] = v1;
        }
    }
}

__global__ __launch_bounds__(256, 2) void qkv_hmma_kernel() {
    const int z = blockIdx.z;
    float* C = (z == 0) ? g_Q : (z == 1) ? g_K : g_V;
    gemm_hmma_body(g_xs, g_Ws + (size_t)z * N_DIM * K_DIM, nullptr, C);
}

__global__ __launch_bounds__(256, 2) void out_hmma_kernel(const float* __restrict__ bo,
                                                          float* __restrict__ out) {
    gemm_hmma_body(g_As, g_Ws + (size_t)3 * N_DIM * K_DIM, bo, out);
}

// ---------------------------------------------------------------------------
// conversions
// ---------------------------------------------------------------------------
// x -> fp16 (single copy)
__global__ void conv_x_kernel(const float* __restrict__ src) {
    const int i = blockIdx.x * blockDim.x + threadIdx.x;
    if (i >= M_ROWS * K_DIM / 4) return;
    float4 v = ((const float4*)src)[i];
    __half2* d = (__half2*)(g_xs) + i * 2;
    d[0] = __floats2half2_rn(v.x, v.y);
    d[1] = __floats2half2_rn(v.z, v.w);
}

// W -> fp16 hi only
__global__ void conv_w_kernel(const float* __restrict__ Wq, const float* __restrict__ Wk,
                              const float* __restrict__ Wv, const float* __restrict__ Wo) {
    const int z = blockIdx.z;
    const float* src = (z == 0) ? Wq : (z == 1) ? Wk : (z == 2) ? Wv : Wo;
    const int i = blockIdx.x * blockDim.x + threadIdx.x;
    if (i >= N_DIM * K_DIM / 4) return;
    float4 v = ((const float4*)src)[i];
    __half2* d = (__half2*)(g_Ws + (size_t)z * N_DIM * K_DIM) + i * 2;
    d[0] = __floats2half2_rn(v.x, v.y);
    d[1] = __floats2half2_rn(v.z, v.w);
}

// bf16 split helper
__device__ __forceinline__ void split4(const float4 v, __nv_bfloat162* h,
                                       __nv_bfloat162* l) {
    const __nv_bfloat16 h0 = __float2bfloat16(v.x);
    const __nv_bfloat16 h1 = __float2bfloat16(v.y);
    const __nv_bfloat16 h2 = __float2bfloat16(v.z);
    const __nv_bfloat16 h3 = __float2bfloat16(v.w);
    h[0] = __nv_bfloat162(h0, h1);
    h[1] = __nv_bfloat162(h2, h3);
    l[0] = __nv_bfloat162(__float2bfloat16(v.x - __bfloat162float(h0)),
                          __float2bfloat16(v.y - __bfloat162float(h1)));
    l[1] = __nv_bfloat162(__float2bfloat16(v.z - __bfloat162float(h2)),
                          __float2bfloat16(v.w - __bfloat162float(h3)));
}

// Q'[bh][t][192] = [hi|hi|lo],  K'[bh][t][192] = [hi|lo|hi]  (bf16)
__global__ void conv_qk_kernel() {
    const int i = blockIdx.x * blockDim.x + threadIdx.x;
    if (i >= M_ROWS * 256) return;
    const int row = i >> 8;
    const int e4  = i & 255;
    const int h   = e4 >> 4;
    const int dd  = (e4 & 15) * 4;
    const int b   = row >> 10, t = row & 1023;
    const size_t base = ((size_t)((b * 16 + h) * 1024) + t) * 192;

    float4 q = *(const float4*)&g_Q[(size_t)row * K_DIM + h * 64 + dd];
    float4 k = *(const float4*)&g_K[(size_t)row * K_DIM + h * 64 + dd];
    __nv_bfloat162 qh[2], ql[2], kh[2], kl[2];
    split4(q, qh, ql);
    split4(k, kh, kl);

    __nv_bfloat162* p;
    p = (__nv_bfloat162*)(g_Qs2 + base + dd);        p[0] = qh[0]; p[1] = qh[1];
    p = (__nv_bfloat162*)(g_Qs2 + base + 64 + dd);   p[0] = qh[0]; p[1] = qh[1];
    p = (__nv_bfloat162*)(g_Qs2 + base + 128 + dd);  p[0] = ql[0]; p[1] = ql[1];

    p = (__nv_bfloat162*)(g_Ks2 + base + dd);        p[0] = kh[0]; p[1] = kh[1];
    p = (__nv_bfloat162*)(g_Ks2 + base + 64 + dd);   p[0] = kl[0]; p[1] = kl[1];
    p = (__nv_bfloat162*)(g_Ks2 + base + 128 + dd);  p[0] = kh[0]; p[1] = kh[1];
}

__global__ void conv_vt_kernel() {
    __shared__ float vs[64][68];
    const int blk = blockIdx.x;
    const int bh = blk >> 4, tt = blk & 15;
    const int b = bh >> 4, h = bh & 15;
    const int t0 = tt * 64;
    const int tid = threadIdx.x;

    const int r  = tid >> 4;
    const int c4 = (tid & 15) * 4;
#pragma unroll
    for (int j = 0; j < 4; j++) {
        const int t = r + j * 16;
        float4 v = *(const float4*)&g_V[(size_t)(b * 1024 + t0 + t) * K_DIM + h * 64 + c4];
        vs[t][c4 + 0] = v.x; vs[t][c4 + 1] = v.y;
        vs[t][c4 + 2] = v.z; vs[t][c4 + 3] = v.w;
    }
    __syncthreads();

    const int d  = tid >> 2;
    const int ts = (tid & 3) * 16;
    const size_t obase = ((size_t)bh * 64 + d) * 1024 + t0 + ts;
#pragma unroll
    for (int j = 0; j < 16; j += 2) {
        const float v0 = vs[ts + j][d];
        const float v1 = vs[ts + j + 1][d];
        const __nv_bfloat16 h0 = __float2bfloat16(v0);
        const __nv_bfloat16 h1 = __float2bfloat16(v1);
        *(__nv_bfloat162*)&g_Vthi[obase + j] = __nv_bfloat162(h0, h1);
        *(__nv_bfloat162*)&g_Vtlo[obase + j] =
            __nv_bfloat162(__float2bfloat16(v0 - __bfloat162float(h0)),
                           __float2bfloat16(v1 - __bfloat162float(h1)));
    }
}

// ---------------------------------------------------------------------------
// HMMA flash attention — EXACT round-7 validated config (bf16 3-product)
// Epilogue writes single fp16 g_As.
// ---------------------------------------------------------------------------
#define QLD 200
#define VLD 136
#define ATTN_SMEM (2 * 128 * QLD * 2 + 2 * 64 * VLD * 2)   // 137216

__global__ __launch_bounds__(256) void attn_hmma_kernel()
{
    extern __shared__ char sm[];
    const uint32_t smb = smem_u32(sm);
    const uint32_t sQ  = smb;
    const uint32_t sK  = smb + 128 * QLD * 2;
    const uint32_t sVh = smb + 2 * 128 * QLD * 2;
    const uint32_t sVl = sVh + 64 * VLD * 2;

    const int tid  = threadIdx.x;
    const int wid  = tid >> 5;
    const int lane = tid & 31;
    const int g    = lane >> 2;
    const int qt   = blockIdx.x;
    const int bh   = blockIdx.y;
    const int b    = bh >> 4;
    const int h    = bh & 15;
    const int cbase = h * DHEAD;
    const int qrow0 = b * TSEQ + qt * 128;

    for (int i = tid; i < 128 * 24; i += 256) {
        const int r = i / 24, s = i % 24;
        cp16(sQ + (r * QLD + s * 8) * 2,
             g_Qs2 + ((size_t)bh * 1024 + qt * 128 + r) * 192 + s * 8);
    }
    CP_COMMIT();

    float acc_o[8][4];
#pragma unroll
    for (int i = 0; i < 8; i++)
#pragma unroll
        for (int r = 0; r < 4; r++) acc_o[i][r] = 0.f;
    float m0 = -INFINITY, m1 = -INFINITY, l0 = 0.f, l1 = 0.f;

    for (int kt = 0; kt < 8; kt++) {
        __syncthreads();
        for (int i = tid; i < 128 * 24; i += 256) {
            const int r = i / 24, s = i % 24;
            cp16(sK + (r * QLD + s * 8) * 2,
                 g_Ks2 + ((size_t)bh * 1024 + kt * 128 + r) * 192 + s * 8);
        }
        for (int i = tid; i < 64 * 16; i += 256) {
            const int r = i / 16, s = i % 16;
            cp16(sVh + (r * VLD + s * 8) * 2,
                 g_Vthi + ((size_t)bh * 64 + r) * 1024 + kt * 128 + s * 8);
            cp16(sVl + (r * VLD + s * 8) * 2,
                 g_Vtlo + ((size_t)bh * 64 + r) * 1024 + kt * 128 + s * 8);
        }
        CP_COMMIT();
        CP_WAIT(0);
        __syncthreads();

        float s_acc[16][4];
#pragma unroll
        for (int ni = 0; ni < 16; ni++)
#pragma unroll
            for (int r = 0; r < 4; r++) s_acc[ni][r] = 0.f;

#pragma unroll
        for (int ks = 0; ks < 12; ks++) {
            uint32_t a[4];
            LDSM_X4(a, sQ + ((wid * 16 + (lane & 15)) * QLD + ks * 16 + (lane >> 4) * 8) * 2);
            uint32_t bf[8][4];
            const int gg = lane >> 3;
#pragma unroll
            for (int np = 0; np < 8; np++) {
                const int row = np * 16 + (gg >> 1) * 8 + (lane & 7);
                LDSM_X4(bf[np], sK + (row * QLD + ks * 16 + (gg & 1) * 8) * 2);
            }
#pragma unroll
            for (int ni = 0; ni < 16; ni++)
                mma16816bf(s_acc[ni], a, &bf[ni >> 1][(ni & 1) * 2]);
        }

        float rm0 = -INFINITY, rm1 = -INFINITY;
#pragma unroll
        for (int ni = 0; ni < 16; ni++) {
            s_acc[ni][0] *= 0.125f; s_acc[ni][1] *= 0.125f;
            s_acc[ni][2] *= 0.125f; s_acc[ni][3] *= 0.125f;
            rm0 = fmaxf(rm0, fmaxf(s_acc[ni][0], s_acc[ni][1]));
            rm1 = fmaxf(rm1, fmaxf(s_acc[ni][2], s_acc[ni][3]));
        }
        rm0 = fmaxf(rm0, __shfl_xor_sync(0xffffffffu, rm0, 1));
        rm0 = fmaxf(rm0, __shfl_xor_sync(0xffffffffu, rm0, 2));
        rm1 = fmaxf(rm1, __shfl_xor_sync(0xffffffffu, rm1, 1));
        rm1 = fmaxf(rm1, __shfl_xor_sync(0xffffffffu, rm1, 2));

        const float nm0 = fmaxf(m0, rm0);
        const float nm1 = fmaxf(m1, rm1);
        const float a0 = __expf(m0 - nm0);
        const float a1 = __expf(m1 - nm1);

        float rs0 = 0.f, rs1 = 0.f;
#pragma unroll
        for (int ni = 0; ni < 16; ni++) {
            s_acc[ni][0] = __expf(s_acc[ni][0] - nm0);
            s_acc[ni][1] = __expf(s_acc[ni][1] - nm0);
            s_acc[ni][2] = __expf(s_acc[ni][2] - nm1);
            s_acc[ni][3] = __expf(s_acc[ni][3] - nm1);
            rs0 += s_acc[ni][0] + s_acc[ni][1];
            rs1 += s_acc[ni][2] + s_acc[ni][3];
        }
        rs0 += __shfl_xor_sync(0xffffffffu, rs0, 1);
        rs0 += __shfl_xor_sync(0xffffffffu, rs0, 2);
        rs1 += __shfl_xor_sync(0xffffffffu, rs1, 1);
        rs1 += __shfl_xor_sync(0xffffffffu, rs1, 2);

        l0 = l0 * a0 + rs0;  m0 = nm0;
        l1 = l1 * a1 + rs1;  m1 = nm1;

#pragma unroll
        for (int ni = 0; ni < 8; ni++) {
            acc_o[ni][0] *= a0; acc_o[ni][1] *= a0;
            acc_o[ni][2] *= a1; acc_o[ni][3] *= a1;
        }

        const int gg = lane >> 3;
#pragma unroll
        for (int ks = 0; ks < 8; ks++) {
            uint32_t ph[4], pl[4];
            {
                const float* t0 = s_acc[2 * ks];
                const float* t1 = s_acc[2 * ks + 1];
                ph[0] = packbf2(t0[0], t0[1]);
                ph[1] = packbf2(t0[2], t0[3]);
                ph[2] = packbf2(t1[0], t1[1]);
                ph[3] = packbf2(t1[2], t1[3]);
                __nv_bfloat162 hb;
                memcpy(&hb, &ph[0], 4);
                pl[0] = packbf2(t0[0] - __bfloat162float(hb.x), t0[1] - __bfloat162float(hb.y));
                memcpy(&hb, &ph[1], 4);
                pl[1] = packbf2(t0[2] - __bfloat162float(hb.x), t0[3] - __bfloat162float(hb.y));
                memcpy(&hb, &ph[2], 4);
                pl[2] = packbf2(t1[0] - __bfloat162float(hb.x), t1[1] - __bfloat162float(hb.y));
                memcpy(&hb, &ph[3], 4);
                pl[3] = packbf2(t1[2] - __bfloat162float(hb.x), t1[3] - __bfloat162float(hb.y));
            }
            uint32_t vh[4][4], vl[4][4];
#pragma unroll
            for (int np = 0; np < 4; np++) {
                const int row = np * 16 + (gg >> 1) * 8 + (lane & 7);
                const int col = ks * 16 + (gg & 1) * 8;
                LDSM_X4(vh[np], sVh + (row * VLD + col) * 2);
                LDSM_X4(vl[np], sVl + (row * VLD + col) * 2);
            }
#pragma unroll
            for (int ni = 0; ni < 8; ni++) {
                mma16816bf(acc_o[ni], ph, &vh[ni >> 1][(ni & 1) * 2]);
                mma16816bf(acc_o[ni], ph, &vl[ni >> 1][(ni & 1) * 2]);
                mma16816bf(acc_o[ni], pl, &vh[ni >> 1][(ni & 1) * 2]);
            }
        }
    }

    // ---- normalize and write single fp16 g_As ----
    const float inv0 = 1.0f / l0;
    const float inv1 = 1.0f / l1;
    const int row0 = qrow0 + wid * 16 + g;
#pragma unroll
    for (int ni = 0; ni < 8; ni++) {
        const int col = cbase + ni * 8 + (lane & 3) * 2;
        *(__half2*)(g_As + (size_t)row0 * K_DIM + col) =
            __floats2half2_rn(acc_o[ni][0] * inv0, acc_o[ni][1] * inv0);
        *(__half2*)(g_As + (size_t)(row0 + 8) * K_DIM + col) =
            __floats2half2_rn(acc_o[ni][2] * inv1, acc_o[ni][3] * inv1);
    }
}

// ---------------------------------------------------------------------------
// kernel_launch
// ---------------------------------------------------------------------------
extern "C" void kernel_launch(void* const* d_in, const int* in_sizes, int n_in,
                              void* d_out, int out_size)
{
    const float* x  = (const float*)d_in[0];
    const float* Wq = (const float*)d_in[1];
    const float* Wk = (const float*)d_in[2];
    const float* Wv = (const float*)d_in[3];
    const float* Wo = (const float*)d_in[4];
    const float* bo = (const float*)d_in[5];
    float* out = (float*)d_out;

    cudaFuncSetAttribute(qkv_hmma_kernel, cudaFuncAttributeMaxDynamicSharedMemorySize, GEMM_SMEM);
    cudaFuncSetAttribute(out_hmma_kernel, cudaFuncAttributeMaxDynamicSharedMemorySize, GEMM_SMEM);
    cudaFuncSetAttribute(attn_hmma_kernel, cudaFuncAttributeMaxDynamicSharedMemorySize, ATTN_SMEM);

    // 1) conversions for projections (fp16 single-product)
    {
        const int nx = M_ROWS * K_DIM / 4;
        conv_x_kernel<<<(nx + 255) / 256, 256>>>(x);
        const int nw = N_DIM * K_DIM / 4;
        conv_w_kernel<<<dim3((nw + 255) / 256, 1, 4), 256>>>(Wq, Wk, Wv, Wo);
    }

    // 2) QKV projections (fp16 HMMA, K=1024)
    qkv_hmma_kernel<<<dim3(N_DIM / GBN, M_ROWS / GBM, 3), 256, GEMM_SMEM>>>();

    // 3) attention operand conversions (bf16 split, round-7 validated)
    conv_qk_kernel<<<(M_ROWS * 256) / 256, 256>>>();
    conv_vt_kernel<<<64 * 16, 256>>>();

    // 4) attention (bf16 3-product HMMA flash, round-7 validated; writes fp16 g_As)
    attn_hmma_kernel<<<dim3(8, 64), 256, ATTN_SMEM>>>();

    // 5) output projection + bias (fp16 HMMA, K=1024)
    out_hmma_kernel<<<dim3(N_DIM / GBN, M_ROWS / GBM), 256, GEMM_SMEM>>>(bo, out);
}

// round 10
// speedup vs baseline: 2.1618x; 1.2376x over previous
#include <cuda_runtime.h>
#include <cuda_bf16.h>
#include <cuda_fp16.h>
#include <math.h>
#include <stdint.h>
#include <string.h>

// ---------------------------------------------------------------------------
// Problem constants
// ---------------------------------------------------------------------------
#define M_ROWS 4096
#define K_DIM  1024
#define N_DIM  1024
#define HEADS  16
#define DHEAD  64
#define TSEQ   1024
#define BATCH  4

// fp32 scratch (attention inputs)
__device__ float g_Q[M_ROWS * K_DIM];
__device__ float g_K[M_ROWS * K_DIM];
__device__ float g_V[M_ROWS * K_DIM];

// fp16 scratch for projection GEMMs (single-product: K = 1024)
__device__ __align__(16) __half g_xs[M_ROWS * K_DIM];
__device__ __align__(16) __half g_As[M_ROWS * K_DIM];
__device__ __align__(16) __half g_Ws[4 * N_DIM * K_DIM];

// attention fp16 operands (2-product)
// Q' per head: [t=1024][128] = [Qh|Qh];  K' per head: [t=1024][128] = [Khi|Klo]
// Vt per head: [d=64][t=1024] hi and lo
__device__ __align__(16) __half g_Qs2[64 * 1024 * 128];
__device__ __align__(16) __half g_Ks2[64 * 1024 * 128];
__device__ __align__(16) __half g_Vthi[64 * 64 * 1024];
__device__ __align__(16) __half g_Vtlo[64 * 64 * 1024];

// ---------------------------------------------------------------------------
// PTX helpers
// ---------------------------------------------------------------------------
__device__ __forceinline__ uint32_t smem_u32(const void* p) {
    uint32_t a;
    asm("{ .reg .u64 t; cvta.to.shared.u64 t, %1; cvt.u32.u64 %0, t; }"
        : "=r"(a) : "l"(p));
    return a;
}
__device__ __forceinline__ void cp16(uint32_t s, const void* g) {
    asm volatile("cp.async.cg.shared.global [%0], [%1], 16;" :: "r"(s), "l"(g));
}
#define CP_COMMIT() asm volatile("cp.async.commit_group;" ::: "memory")
#define CP_WAIT(n)  asm volatile("cp.async.wait_group %0;" :: "n"(n) : "memory")

#define LDSM_X4(r, addr)                                                       \
    asm volatile("ldmatrix.sync.aligned.m8n8.x4.shared.b16 {%0,%1,%2,%3}, [%4];" \
                 : "=r"((r)[0]), "=r"((r)[1]), "=r"((r)[2]), "=r"((r)[3])      \
                 : "r"(addr))

__device__ __forceinline__ void mma16816h(float* c, const uint32_t* a,
                                          const uint32_t* b) {
    asm volatile(
        "mma.sync.aligned.m16n8k16.row.col.f32.f16.f16.f32 "
        "{%0,%1,%2,%3}, {%4,%5,%6,%7}, {%8,%9}, {%0,%1,%2,%3};"
        : "+f"(c[0]), "+f"(c[1]), "+f"(c[2]), "+f"(c[3])
        : "r"(a[0]), "r"(a[1]), "r"(a[2]), "r"(a[3]), "r"(b[0]), "r"(b[1]));
}

__device__ __forceinline__ uint32_t packh2(float x, float y) {
    __half2 t = __floats2half2_rn(x, y);
    uint32_t u;
    memcpy(&u, &t, 4);
    return u;
}

// ---------------------------------------------------------------------------
// HMMA fp16 NT GEMM: C[M,N] = A[M,1024] @ B[N,1024]^T (+ bias)
// (round-9 validated, unchanged)
// ---------------------------------------------------------------------------
#define GBM 128
#define GBN 128
#define GBK 64
#define TILE_B  (128 * 128)
#define STAGE_B (2 * TILE_B)
#define NSTAGE  3
#define NCH     (K_DIM / GBK)            // 16
#define GEMM_SMEM (NSTAGE * STAGE_B)     // 98304

__device__ __forceinline__ uint32_t swz(uint32_t row, uint32_t seg) {
    return row * 128 + ((seg ^ (row & 7)) * 16);
}

__device__ __forceinline__ void load_chunk(const __half* __restrict__ A,
                                           const __half* __restrict__ B,
                                           int bm, int bn, int k0,
                                           uint32_t sA, uint32_t sB) {
    const int tid = threadIdx.x;
    const int row = tid >> 1;
    const int sb  = (tid & 1) * 4;
#pragma unroll
    for (int j = 0; j < 4; j++) {
        const int seg = sb + j;
        cp16(sA + swz(row, seg), A + (size_t)(bm + row) * K_DIM + k0 + seg * 8);
        cp16(sB + swz(row, seg), B + (size_t)(bn + row) * K_DIM + k0 + seg * 8);
    }
    CP_COMMIT();
}

__device__ void gemm_hmma_body(const __half* __restrict__ A,
                               const __half* __restrict__ B,
                               const float* __restrict__ bias,
                               float* __restrict__ C) {
    extern __shared__ char sm[];
    const uint32_t smb = smem_u32(sm);

    const int tid  = threadIdx.x;
    const int wid  = tid >> 5;
    const int lane = tid & 31;
    const int wm   = wid >> 2;
    const int wn   = wid & 3;
    const int bm   = blockIdx.y * GBM;
    const int bn   = blockIdx.x * GBN;

    float acc[4][4][4];
#pragma unroll
    for (int i = 0; i < 4; i++)
#pragma unroll
        for (int j = 0; j < 4; j++)
#pragma unroll
            for (int r = 0; r < 4; r++) acc[i][j][r] = 0.f;

#pragma unroll
    for (int s = 0; s < NSTAGE; s++)
        load_chunk(A, B, bm, bn, s * GBK,
                   smb + s * STAGE_B, smb + s * STAGE_B + TILE_B);

    for (int c = 0; c < NCH; c++) {
        const int rem = NCH - 1 - c;
        if (rem >= 2)      CP_WAIT(2);
        else if (rem == 1) CP_WAIT(1);
        else               CP_WAIT(0);
        __syncthreads();

        const uint32_t aB = smb + (c % NSTAGE) * STAGE_B;
        const uint32_t bB = aB + TILE_B;

#pragma unroll
        for (int ks = 0; ks < 4; ks++) {
            uint32_t afr[4][4];
#pragma unroll
            for (int mi = 0; mi < 4; mi++) {
                const int row = wm * 64 + mi * 16 + (lane & 15);
                const int seg = ks * 2 + (lane >> 4);
                LDSM_X4(afr[mi], aB + swz(row, seg));
            }
            uint32_t bfr[2][4];
            const int g = lane >> 3;
#pragma unroll
            for (int np = 0; np < 2; np++) {
                const int row = wn * 32 + np * 16 + (g >> 1) * 8 + (lane & 7);
                const int seg = ks * 2 + (g & 1);
                LDSM_X4(bfr[np], bB + swz(row, seg));
            }
#pragma unroll
            for (int mi = 0; mi < 4; mi++) {
#pragma unroll
                for (int ni = 0; ni < 4; ni++)
                    mma16816h(acc[mi][ni], afr[mi], &bfr[ni >> 1][(ni & 1) * 2]);
            }
        }
        __syncthreads();

        if (c + NSTAGE < NCH)
            load_chunk(A, B, bm, bn, (c + NSTAGE) * GBK,
                       smb + (c % NSTAGE) * STAGE_B,
                       smb + (c % NSTAGE) * STAGE_B + TILE_B);
    }

#pragma unroll
    for (int mi = 0; mi < 4; mi++) {
#pragma unroll
        for (int ni = 0; ni < 4; ni++) {
            const int r0 = bm + wm * 64 + mi * 16 + (lane >> 2);
            const int c0 = bn + wn * 32 + ni * 8 + (lane & 3) * 2;
            float2 v0 = make_float2(acc[mi][ni][0], acc[mi][ni][1]);
            float2 v1 = make_float2(acc[mi][ni][2], acc[mi][ni][3]);
            if (bias) {
                const float b0 = bias[c0], b1 = bias[c0 + 1];
                v0.x += b0; v0.y += b1;
                v1.x += b0; v1.y += b1;
            }
            *(float2*)&C[(size_t)r0 * N_DIM + c0]       = v0;
            *(float2*)&C[(size_t)(r0 + 8) * N_DIM + c0] = v1;
        }
    }
}

__global__ __launch_bounds__(256, 2) void qkv_hmma_kernel() {
    const int z = blockIdx.z;
    float* C = (z == 0) ? g_Q : (z == 1) ? g_K : g_V;
    gemm_hmma_body(g_xs, g_Ws + (size_t)z * N_DIM * K_DIM, nullptr, C);
}

__global__ __launch_bounds__(256, 2) void out_hmma_kernel(const float* __restrict__ bo,
                                                          float* __restrict__ out) {
    gemm_hmma_body(g_As, g_Ws + (size_t)3 * N_DIM * K_DIM, bo, out);
}

// ---------------------------------------------------------------------------
// conversions
// ---------------------------------------------------------------------------
// x -> fp16 (single copy)
__global__ void conv_x_kernel(const float* __restrict__ src) {
    const int i = blockIdx.x * blockDim.x + threadIdx.x;
    if (i >= M_ROWS * K_DIM / 4) return;
    float4 v = ((const float4*)src)[i];
    __half2* d = (__half2*)(g_xs) + i * 2;
    d[0] = __floats2half2_rn(v.x, v.y);
    d[1] = __floats2half2_rn(v.z, v.w);
}

// W -> fp16 hi only
__global__ void conv_w_kernel(const float* __restrict__ Wq, const float* __restrict__ Wk,
                              const float* __restrict__ Wv, const float* __restrict__ Wo) {
    const int z = blockIdx.z;
    const float* src = (z == 0) ? Wq : (z == 1) ? Wk : (z == 2) ? Wv : Wo;
    const int i = blockIdx.x * blockDim.x + threadIdx.x;
    if (i >= N_DIM * K_DIM / 4) return;
    float4 v = ((const float4*)src)[i];
    __half2* d = (__half2*)(g_Ws + (size_t)z * N_DIM * K_DIM) + i * 2;
    d[0] = __floats2half2_rn(v.x, v.y);
    d[1] = __floats2half2_rn(v.z, v.w);
}

// Q'[bh][t][128] = [Qh|Qh],  K'[bh][t][128] = [Khi|Klo]  (fp16)
__global__ void conv_qk_kernel() {
    const int i = blockIdx.x * blockDim.x + threadIdx.x;
    if (i >= M_ROWS * 256) return;
    const int row = i >> 8;
    const int e4  = i & 255;
    const int h   = e4 >> 4;
    const int dd  = (e4 & 15) * 4;
    const int b   = row >> 10, t = row & 1023;
    const size_t base = ((size_t)((b * 16 + h) * 1024) + t) * 128;

    float4 q = *(const float4*)&g_Q[(size_t)row * K_DIM + h * 64 + dd];
    float4 k = *(const float4*)&g_K[(size_t)row * K_DIM + h * 64 + dd];

    const __half2 qh0 = __floats2half2_rn(q.x, q.y);
    const __half2 qh1 = __floats2half2_rn(q.z, q.w);
    const __half kx = __float2half_rn(k.x);
    const __half ky = __float2half_rn(k.y);
    const __half kz = __float2half_rn(k.z);
    const __half kw = __float2half_rn(k.w);

    __half2* p;
    p = (__half2*)(g_Qs2 + base + dd);       p[0] = qh0; p[1] = qh1;
    p = (__half2*)(g_Qs2 + base + 64 + dd);  p[0] = qh0; p[1] = qh1;

    p = (__half2*)(g_Ks2 + base + dd);
    p[0] = __half2(kx, ky);
    p[1] = __half2(kz, kw);
    p = (__half2*)(g_Ks2 + base + 64 + dd);
    p[0] = __half2(__float2half_rn(k.x - __half2float(kx)),
                   __float2half_rn(k.y - __half2float(ky)));
    p[1] = __half2(__float2half_rn(k.z - __half2float(kz)),
                   __float2half_rn(k.w - __half2float(kw)));
}

// Vt[bh][d][t] hi/lo fp16 — transposed per head via smem tile
__global__ void conv_vt_kernel() {
    __shared__ float vs[64][68];
    const int blk = blockIdx.x;
    const int bh = blk >> 4, tt = blk & 15;
    const int b = bh >> 4, h = bh & 15;
    const int t0 = tt * 64;
    const int tid = threadIdx.x;

    const int r  = tid >> 4;
    const int c4 = (tid & 15) * 4;
#pragma unroll
    for (int j = 0; j < 4; j++) {
        const int t = r + j * 16;
        float4 v = *(const float4*)&g_V[(size_t)(b * 1024 + t0 + t) * K_DIM + h * 64 + c4];
        vs[t][c4 + 0] = v.x; vs[t][c4 + 1] = v.y;
        vs[t][c4 + 2] = v.z; vs[t][c4 + 3] = v.w;
    }
    __syncthreads();

    const int d  = tid >> 2;
    const int ts = (tid & 3) * 16;
    const size_t obase = ((size_t)bh * 64 + d) * 1024 + t0 + ts;
#pragma unroll
    for (int j = 0; j < 16; j += 2) {
        const float v0 = vs[ts + j][d];
        const float v1 = vs[ts + j + 1][d];
        const __half h0 = __float2half_rn(v0);
        const __half h1 = __float2half_rn(v1);
        *(__half2*)&g_Vthi[obase + j] = __half2(h0, h1);
        *(__half2*)&g_Vtlo[obase + j] =
            __half2(__float2half_rn(v0 - __half2float(h0)),
                    __float2half_rn(v1 - __half2float(h1)));
    }
}

// ---------------------------------------------------------------------------
// HMMA flash attention, fp16 2-product:
//   S = Qh·Khi + Qh·Klo  (K'=128, 8 k-steps)
//   O += Ph·Vhi + Ph·Vlo
// smem PADDED to 116 KB to force 1 CTA/SM (round-8 regression containment).
// Epilogue writes single fp16 g_As.
// ---------------------------------------------------------------------------
#define QLD 136
#define VLD 136
#define ATTN_SMEM_USED ((2 * 128 * QLD + 2 * 64 * VLD) * 2)   // 104448
#define ATTN_SMEM 118784                                      // 116 KB: 1 CTA/SM

__global__ __launch_bounds__(256, 1) void attn_hmma_kernel()
{
    extern __shared__ char sm[];
    const uint32_t smb = smem_u32(sm);
    const uint32_t sQ  = smb;
    const uint32_t sK  = smb + 128 * QLD * 2;
    const uint32_t sVh = smb + 2 * 128 * QLD * 2;
    const uint32_t sVl = sVh + 64 * VLD * 2;

    const int tid  = threadIdx.x;
    const int wid  = tid >> 5;
    const int lane = tid & 31;
    const int g    = lane >> 2;
    const int qt   = blockIdx.x;
    const int bh   = blockIdx.y;
    const int b    = bh >> 4;
    const int h    = bh & 15;
    const int cbase = h * DHEAD;
    const int qrow0 = b * TSEQ + qt * 128;

    // load Q' tile (128 x 128 fp16) once
    for (int i = tid; i < 128 * 16; i += 256) {
        const int r = i >> 4, s = i & 15;
        cp16(sQ + (r * QLD + s * 8) * 2,
             g_Qs2 + ((size_t)bh * 1024 + qt * 128 + r) * 128 + s * 8);
    }
    CP_COMMIT();

    float acc_o[8][4];
#pragma unroll
    for (int i = 0; i < 8; i++)
#pragma unroll
        for (int r = 0; r < 4; r++) acc_o[i][r] = 0.f;
    float m0 = -INFINITY, m1 = -INFINITY, l0 = 0.f, l1 = 0.f;

    for (int kt = 0; kt < 8; kt++) {
        __syncthreads();
        for (int i = tid; i < 128 * 16; i += 256) {
            const int r = i >> 4, s = i & 15;
            cp16(sK + (r * QLD + s * 8) * 2,
                 g_Ks2 + ((size_t)bh * 1024 + kt * 128 + r) * 128 + s * 8);
        }
        for (int i = tid; i < 64 * 16; i += 256) {
            const int r = i >> 4, s = i & 15;
            cp16(sVh + (r * VLD + s * 8) * 2,
                 g_Vthi + ((size_t)bh * 64 + r) * 1024 + kt * 128 + s * 8);
            cp16(sVl + (r * VLD + s * 8) * 2,
                 g_Vtlo + ((size_t)bh * 64 + r) * 1024 + kt * 128 + s * 8);
        }
        CP_COMMIT();
        CP_WAIT(0);
        __syncthreads();

        // ---- S = Q' K'^T : 8 k-steps ----
        float s_acc[16][4];
#pragma unroll
        for (int ni = 0; ni < 16; ni++)
#pragma unroll
            for (int r = 0; r < 4; r++) s_acc[ni][r] = 0.f;

#pragma unroll
        for (int ks = 0; ks < 8; ks++) {
            uint32_t a[4];
            LDSM_X4(a, sQ + ((wid * 16 + (lane & 15)) * QLD + ks * 16 + (lane >> 4) * 8) * 2);
            uint32_t bf[8][4];
            const int gg = lane >> 3;
#pragma unroll
            for (int np = 0; np < 8; np++) {
                const int row = np * 16 + (gg >> 1) * 8 + (lane & 7);
                LDSM_X4(bf[np], sK + (row * QLD + ks * 16 + (gg & 1) * 8) * 2);
            }
#pragma unroll
            for (int ni = 0; ni < 16; ni++)
                mma16816h(s_acc[ni], a, &bf[ni >> 1][(ni & 1) * 2]);
        }

        // ---- online softmax ----
        float rm0 = -INFINITY, rm1 = -INFINITY;
#pragma unroll
        for (int ni = 0; ni < 16; ni++) {
            s_acc[ni][0] *= 0.125f; s_acc[ni][1] *= 0.125f;
            s_acc[ni][2] *= 0.125f; s_acc[ni][3] *= 0.125f;
            rm0 = fmaxf(rm0, fmaxf(s_acc[ni][0], s_acc[ni][1]));
            rm1 = fmaxf(rm1, fmaxf(s_acc[ni][2], s_acc[ni][3]));
        }
        rm0 = fmaxf(rm0, __shfl_xor_sync(0xffffffffu, rm0, 1));
        rm0 = fmaxf(rm0, __shfl_xor_sync(0xffffffffu, rm0, 2));
        rm1 = fmaxf(rm1, __shfl_xor_sync(0xffffffffu, rm1, 1));
        rm1 = fmaxf(rm1, __shfl_xor_sync(0xffffffffu, rm1, 2));

        const float nm0 = fmaxf(m0, rm0);
        const float nm1 = fmaxf(m1, rm1);
        const float a0 = __expf(m0 - nm0);
        const float a1 = __expf(m1 - nm1);

        float rs0 = 0.f, rs1 = 0.f;
#pragma unroll
        for (int ni = 0; ni < 16; ni++) {
            s_acc[ni][0] = __expf(s_acc[ni][0] - nm0);
            s_acc[ni][1] = __expf(s_acc[ni][1] - nm0);
            s_acc[ni][2] = __expf(s_acc[ni][2] - nm1);
            s_acc[ni][3] = __expf(s_acc[ni][3] - nm1);
            rs0 += s_acc[ni][0] + s_acc[ni][1];
            rs1 += s_acc[ni][2] + s_acc[ni][3];
        }
        rs0 += __shfl_xor_sync(0xffffffffu, rs0, 1);
        rs0 += __shfl_xor_sync(0xffffffffu, rs0, 2);
        rs1 += __shfl_xor_sync(0xffffffffu, rs1, 1);
        rs1 += __shfl_xor_sync(0xffffffffu, rs1, 2);

        l0 = l0 * a0 + rs0;  m0 = nm0;
        l1 = l1 * a1 + rs1;  m1 = nm1;

#pragma unroll
        for (int ni = 0; ni < 8; ni++) {
            acc_o[ni][0] *= a0; acc_o[ni][1] *= a0;
            acc_o[ni][2] *= a1; acc_o[ni][3] *= a1;
        }

        // ---- O += P V (P fp16, V hi+lo) ----
        const int gg = lane >> 3;
#pragma unroll
        for (int ks = 0; ks < 8; ks++) {
            uint32_t ph[4];
            {
                const float* t0 = s_acc[2 * ks];
                const float* t1 = s_acc[2 * ks + 1];
                ph[0] = packh2(t0[0], t0[1]);
                ph[1] = packh2(t0[2], t0[3]);
                ph[2] = packh2(t1[0], t1[1]);
                ph[3] = packh2(t1[2], t1[3]);
            }
            uint32_t vh[4][4], vl[4][4];
#pragma unroll
            for (int np = 0; np < 4; np++) {
                const int row = np * 16 + (gg >> 1) * 8 + (lane & 7);
                const int col = ks * 16 + (gg & 1) * 8;
                LDSM_X4(vh[np], sVh + (row * VLD + col) * 2);
                LDSM_X4(vl[np], sVl + (row * VLD + col) * 2);
            }
#pragma unroll
            for (int ni = 0; ni < 8; ni++) {
                mma16816h(acc_o[ni], ph, &vh[ni >> 1][(ni & 1) * 2]);
                mma16816h(acc_o[ni], ph, &vl[ni >> 1][(ni & 1) * 2]);
            }
        }
    }

    // ---- normalize and write single fp16 g_As ----
    const float inv0 = 1.0f / l0;
    const float inv1 = 1.0f / l1;
    const int row0 = qrow0 + wid * 16 + g;
#pragma unroll
    for (int ni = 0; ni < 8; ni++) {
        const int col = cbase + ni * 8 + (lane & 3) * 2;
        *(__half2*)(g_As + (size_t)row0 * K_DIM + col) =
            __floats2half2_rn(acc_o[ni][0] * inv0, acc_o[ni][1] * inv0);
        *(__half2*)(g_As + (size_t)(row0 + 8) * K_DIM + col) =
            __floats2half2_rn(acc_o[ni][2] * inv1, acc_o[ni][3] * inv1);
    }
}

// ---------------------------------------------------------------------------
// kernel_launch
// ---------------------------------------------------------------------------
extern "C" void kernel_launch(void* const* d_in, const int* in_sizes, int n_in,
                              void* d_out, int out_size)
{
    const float* x  = (const float*)d_in[0];
    const float* Wq = (const float*)d_in[1];
    const float* Wk = (const float*)d_in[2];
    const float* Wv = (const float*)d_in[3];
    const float* Wo = (const float*)d_in[4];
    const float* bo = (const float*)d_in[5];
    float* out = (float*)d_out;

    cudaFuncSetAttribute(qkv_hmma_kernel, cudaFuncAttributeMaxDynamicSharedMemorySize, GEMM_SMEM);
    cudaFuncSetAttribute(out_hmma_kernel, cudaFuncAttributeMaxDynamicSharedMemorySize, GEMM_SMEM);
    cudaFuncSetAttribute(attn_hmma_kernel, cudaFuncAttributeMaxDynamicSharedMemorySize, ATTN_SMEM);

    // 1) conversions for projections (fp16 single-product)
    {
        const int nx = M_ROWS * K_DIM / 4;
        conv_x_kernel<<<(nx + 255) / 256, 256>>>(x);
        const int nw = N_DIM * K_DIM / 4;
        conv_w_kernel<<<dim3((nw + 255) / 256, 1, 4), 256>>>(Wq, Wk, Wv, Wo);
    }

    // 2) QKV projections (fp16 HMMA, K=1024)
    qkv_hmma_kernel<<<dim3(N_DIM / GBN, M_ROWS / GBM, 3), 256, GEMM_SMEM>>>();

    // 3) attention operand conversions (fp16 2-product)
    conv_qk_kernel<<<(M_ROWS * 256) / 256, 256>>>();
    conv_vt_kernel<<<64 * 16, 256>>>();

    // 4) attention (fp16 2-product HMMA flash, 1 CTA/SM forced; writes fp16 g_As)
    attn_hmma_kernel<<<dim3(8, 64), 256, ATTN_SMEM>>>();

    // 5) output projection + bias (fp16 HMMA, K=1024)
    out_hmma_kernel<<<dim3(N_DIM / GBN, M_ROWS / GBM), 256, GEMM_SMEM>>>(bo, out);
}

// round 11
// speedup vs baseline: 2.7698x; 1.2812x over previous
#include <cuda_runtime.h>
#include <cuda_bf16.h>
#include <cuda_fp16.h>
#include <math.h>
#include <stdint.h>
#include <string.h>

// ---------------------------------------------------------------------------
// Problem constants
// ---------------------------------------------------------------------------
#define M_ROWS 4096
#define K_DIM  1024
#define N_DIM  1024
#define HEADS  16
#define DHEAD  64
#define TSEQ   1024
#define BATCH  4

// fp32 scratch (V only; Q/K go straight to fp16 per-head layouts)
__device__ float g_V[M_ROWS * K_DIM];

// fp16 scratch for projection GEMMs
__device__ __align__(16) __half g_xs[M_ROWS * K_DIM];
__device__ __align__(16) __half g_As[M_ROWS * K_DIM];
__device__ __align__(16) __half g_Ws[4 * N_DIM * K_DIM];

// attention fp16 operands (single-product)
// Q'/K' per head: [t=1024][64];  Vt per head: [d=64][t=1024]
__device__ __align__(16) __half g_Qs2[64 * 1024 * 64];
__device__ __align__(16) __half g_Ks2[64 * 1024 * 64];
__device__ __align__(16) __half g_Vthi[64 * 64 * 1024];

// ---------------------------------------------------------------------------
// PTX helpers
// ---------------------------------------------------------------------------
__device__ __forceinline__ uint32_t smem_u32(const void* p) {
    uint32_t a;
    asm("{ .reg .u64 t; cvta.to.shared.u64 t, %1; cvt.u32.u64 %0, t; }"
        : "=r"(a) : "l"(p));
    return a;
}
__device__ __forceinline__ void cp16(uint32_t s, const void* g) {
    asm volatile("cp.async.cg.shared.global [%0], [%1], 16;" :: "r"(s), "l"(g));
}
#define CP_COMMIT() asm volatile("cp.async.commit_group;" ::: "memory")
#define CP_WAIT(n)  asm volatile("cp.async.wait_group %0;" :: "n"(n) : "memory")

#define LDSM_X4(r, addr)                                                       \
    asm volatile("ldmatrix.sync.aligned.m8n8.x4.shared.b16 {%0,%1,%2,%3}, [%4];" \
                 : "=r"((r)[0]), "=r"((r)[1]), "=r"((r)[2]), "=r"((r)[3])      \
                 : "r"(addr))

__device__ __forceinline__ void mma16816h(float* c, const uint32_t* a,
                                          const uint32_t* b) {
    asm volatile(
        "mma.sync.aligned.m16n8k16.row.col.f32.f16.f16.f32 "
        "{%0,%1,%2,%3}, {%4,%5,%6,%7}, {%8,%9}, {%0,%1,%2,%3};"
        : "+f"(c[0]), "+f"(c[1]), "+f"(c[2]), "+f"(c[3])
        : "r"(a[0]), "r"(a[1]), "r"(a[2]), "r"(a[3]), "r"(b[0]), "r"(b[1]));
}

__device__ __forceinline__ uint32_t packh2(float x, float y) {
    __half2 t = __floats2half2_rn(x, y);
    uint32_t u;
    memcpy(&u, &t, 4);
    return u;
}

// ---------------------------------------------------------------------------
// HMMA fp16 NT GEMM: C = A[M,1024] @ B[N,1024]^T
// Store modes: 0 = fp32 C (+ optional bias); 1 = Q' per-head fp16; 2 = K'.
// ---------------------------------------------------------------------------
#define GBM 128
#define GBN 128
#define GBK 64
#define TILE_B  (128 * 128)
#define STAGE_B (2 * TILE_B)
#define NSTAGE  3
#define NCH     (K_DIM / GBK)            // 16
#define GEMM_SMEM (NSTAGE * STAGE_B)     // 98304

__device__ __forceinline__ uint32_t swz(uint32_t row, uint32_t seg) {
    return row * 128 + ((seg ^ (row & 7)) * 16);
}

__device__ __forceinline__ void load_chunk(const __half* __restrict__ A,
                                           const __half* __restrict__ B,
                                           int bm, int bn, int k0,
                                           uint32_t sA, uint32_t sB) {
    const int tid = threadIdx.x;
    const int row = tid >> 1;
    const int sb  = (tid & 1) * 4;
#pragma unroll
    for (int j = 0; j < 4; j++) {
        const int seg = sb + j;
        cp16(sA + swz(row, seg), A + (size_t)(bm + row) * K_DIM + k0 + seg * 8);
        cp16(sB + swz(row, seg), B + (size_t)(bn + row) * K_DIM + k0 + seg * 8);
    }
    CP_COMMIT();
}

template <int MODE>
__device__ void gemm_hmma_body(const __half* __restrict__ A,
                               const __half* __restrict__ B,
                               const float* __restrict__ bias,
                               float* __restrict__ C,
                               __half* __restrict__ Ch) {
    extern __shared__ char sm[];
    const uint32_t smb = smem_u32(sm);

    const int tid  = threadIdx.x;
    const int wid  = tid >> 5;
    const int lane = tid & 31;
    const int wm   = wid >> 2;
    const int wn   = wid & 3;
    const int bm   = blockIdx.y * GBM;
    const int bn   = blockIdx.x * GBN;

    float acc[4][4][4];
#pragma unroll
    for (int i = 0; i < 4; i++)
#pragma unroll
        for (int j = 0; j < 4; j++)
#pragma unroll
            for (int r = 0; r < 4; r++) acc[i][j][r] = 0.f;

#pragma unroll
    for (int s = 0; s < NSTAGE; s++)
        load_chunk(A, B, bm, bn, s * GBK,
                   smb + s * STAGE_B, smb + s * STAGE_B + TILE_B);

    for (int c = 0; c < NCH; c++) {
        const int rem = NCH - 1 - c;
        if (rem >= 2)      CP_WAIT(2);
        else if (rem == 1) CP_WAIT(1);
        else               CP_WAIT(0);
        __syncthreads();

        const uint32_t aB = smb + (c % NSTAGE) * STAGE_B;
        const uint32_t bB = aB + TILE_B;

#pragma unroll
        for (int ks = 0; ks < 4; ks++) {
            uint32_t afr[4][4];
#pragma unroll
            for (int mi = 0; mi < 4; mi++) {
                const int row = wm * 64 + mi * 16 + (lane & 15);
                const int seg = ks * 2 + (lane >> 4);
                LDSM_X4(afr[mi], aB + swz(row, seg));
            }
            uint32_t bfr[2][4];
            const int g = lane >> 3;
#pragma unroll
            for (int np = 0; np < 2; np++) {
                const int row = wn * 32 + np * 16 + (g >> 1) * 8 + (lane & 7);
                const int seg = ks * 2 + (g & 1);
                LDSM_X4(bfr[np], bB + swz(row, seg));
            }
#pragma unroll
            for (int mi = 0; mi < 4; mi++) {
#pragma unroll
                for (int ni = 0; ni < 4; ni++)
                    mma16816h(acc[mi][ni], afr[mi], &bfr[ni >> 1][(ni & 1) * 2]);
            }
        }
        __syncthreads();

        if (c + NSTAGE < NCH)
            load_chunk(A, B, bm, bn, (c + NSTAGE) * GBK,
                       smb + (c % NSTAGE) * STAGE_B,
                       smb + (c % NSTAGE) * STAGE_B + TILE_B);
    }

#pragma unroll
    for (int mi = 0; mi < 4; mi++) {
#pragma unroll
        for (int ni = 0; ni < 4; ni++) {
            const int r0 = bm + wm * 64 + mi * 16 + (lane >> 2);
            const int c0 = bn + wn * 32 + ni * 8 + (lane & 3) * 2;
            if (MODE == 0) {
                float2 v0 = make_float2(acc[mi][ni][0], acc[mi][ni][1]);
                float2 v1 = make_float2(acc[mi][ni][2], acc[mi][ni][3]);
                if (bias) {
                    const float b0 = bias[c0], b1 = bias[c0 + 1];
                    v0.x += b0; v0.y += b1;
                    v1.x += b0; v1.y += b1;
                }
                *(float2*)&C[(size_t)r0 * N_DIM + c0]       = v0;
                *(float2*)&C[(size_t)(r0 + 8) * N_DIM + c0] = v1;
            } else {
                // per-head fp16 layout: [b*16+h][t][64]
                const int b  = r0 >> 10;
                const int t  = r0 & 1023;
                const int h  = c0 >> 6;
                const int dd = c0 & 63;
                const size_t base = (((size_t)(b * 16 + h) * 1024 + t) << 6) + dd;
                *(__half2*)&Ch[base] =
                    __floats2half2_rn(acc[mi][ni][0], acc[mi][ni][1]);
                *(__half2*)&Ch[base + (8 << 6)] =
                    __floats2half2_rn(acc[mi][ni][2], acc[mi][ni][3]);
            }
        }
    }
}

__global__ __launch_bounds__(256, 2) void qkv_hmma_kernel() {
    const int z = blockIdx.z;
    if (z == 0)
        gemm_hmma_body<1>(g_xs, g_Ws, nullptr, nullptr, g_Qs2);
    else if (z == 1)
        gemm_hmma_body<2>(g_xs, g_Ws + (size_t)N_DIM * K_DIM, nullptr, nullptr, g_Ks2);
    else
        gemm_hmma_body<0>(g_xs, g_Ws + (size_t)2 * N_DIM * K_DIM, nullptr, g_V, nullptr);
}

__global__ __launch_bounds__(256, 2) void out_hmma_kernel(const float* __restrict__ bo,
                                                          float* __restrict__ out) {
    gemm_hmma_body<0>(g_As, g_Ws + (size_t)3 * N_DIM * K_DIM, bo, out, nullptr);
}

// ---------------------------------------------------------------------------
// conversions
// ---------------------------------------------------------------------------
__global__ void conv_x_kernel(const float* __restrict__ src) {
    const int i = blockIdx.x * blockDim.x + threadIdx.x;
    if (i >= M_ROWS * K_DIM / 4) return;
    float4 v = ((const float4*)src)[i];
    __half2* d = (__half2*)(g_xs) + i * 2;
    d[0] = __floats2half2_rn(v.x, v.y);
    d[1] = __floats2half2_rn(v.z, v.w);
}

__global__ void conv_w_kernel(const float* __restrict__ Wq, const float* __restrict__ Wk,
                              const float* __restrict__ Wv, const float* __restrict__ Wo) {
    const int z = blockIdx.z;
    const float* src = (z == 0) ? Wq : (z == 1) ? Wk : (z == 2) ? Wv : Wo;
    const int i = blockIdx.x * blockDim.x + threadIdx.x;
    if (i >= N_DIM * K_DIM / 4) return;
    float4 v = ((const float4*)src)[i];
    __half2* d = (__half2*)(g_Ws + (size_t)z * N_DIM * K_DIM) + i * 2;
    d[0] = __floats2half2_rn(v.x, v.y);
    d[1] = __floats2half2_rn(v.z, v.w);
}

// Vt[bh][d][t] fp16 — transposed per head via smem tile
__global__ void conv_vt_kernel() {
    __shared__ float vs[64][68];
    const int blk = blockIdx.x;
    const int bh = blk >> 4, tt = blk & 15;
    const int b = bh >> 4, h = bh & 15;
    const int t0 = tt * 64;
    const int tid = threadIdx.x;

    const int r  = tid >> 4;
    const int c4 = (tid & 15) * 4;
#pragma unroll
    for (int j = 0; j < 4; j++) {
        const int t = r + j * 16;
        float4 v = *(const float4*)&g_V[(size_t)(b * 1024 + t0 + t) * K_DIM + h * 64 + c4];
        vs[t][c4 + 0] = v.x; vs[t][c4 + 1] = v.y;
        vs[t][c4 + 2] = v.z; vs[t][c4 + 3] = v.w;
    }
    __syncthreads();

    const int d  = tid >> 2;
    const int ts = (tid & 3) * 16;
    const size_t obase = ((size_t)bh * 64 + d) * 1024 + t0 + ts;
#pragma unroll
    for (int j = 0; j < 16; j += 2)
        *(__half2*)&g_Vthi[obase + j] =
            __floats2half2_rn(vs[ts + j][d], vs[ts + j + 1][d]);
}

// ---------------------------------------------------------------------------
// HMMA flash attention, single-product fp16:
//   S = Qh·Kh^T  (K'=64, 4 k-steps);  O += Ph·Vh (8 k-steps)
// 2-stage K/V cp.async pipeline; smem padded to 116 KB -> 1 CTA/SM.
// Epilogue writes fp16 g_As.
// ---------------------------------------------------------------------------
#define QLD 72     // Q/K smem pitch (fp16 elems), 144B rows
#define VLD 136    // Vt pitch
#define K_STAGE_B (128 * QLD * 2)            // 18432
#define V_STAGE_B (64 * VLD * 2)             // 17408
#define KV_STAGE_B (K_STAGE_B + V_STAGE_B)   // 35840
#define ATTN_SMEM 118784                     // pad to 116 KB: 1 CTA/SM

__device__ __forceinline__ void attn_load_q(uint32_t sQ, int bh, int qt) {
    const int tid = threadIdx.x;
#pragma unroll
    for (int j = 0; j < 4; j++) {
        const int i = tid + j * 256;         // 0..1023
        const int r = i >> 3, s = i & 7;
        cp16(sQ + (r * QLD + s * 8) * 2,
             g_Qs2 + (((size_t)bh * 1024 + qt * 128 + r) << 6) + s * 8);
    }
}
__device__ __forceinline__ void attn_load_kv(uint32_t sKV, int bh, int kt) {
    const int tid = threadIdx.x;
#pragma unroll
    for (int j = 0; j < 4; j++) {
        const int i = tid + j * 256;
        const int r = i >> 3, s = i & 7;
        cp16(sKV + (r * QLD + s * 8) * 2,
             g_Ks2 + (((size_t)bh * 1024 + kt * 128 + r) << 6) + s * 8);
    }
    const uint32_t sV = sKV + K_STAGE_B;
#pragma unroll
    for (int j = 0; j < 4; j++) {
        const int i = tid + j * 256;
        const int r = i >> 4, s = i & 15;
        cp16(sV + (r * VLD + s * 8) * 2,
             g_Vthi + ((size_t)bh * 64 + r) * 1024 + kt * 128 + s * 8);
    }
    CP_COMMIT();
}

__global__ __launch_bounds__(256, 1) void attn_hmma_kernel()
{
    extern __shared__ char sm[];
    const uint32_t smb = smem_u32(sm);
    const uint32_t sQ   = smb;
    const uint32_t sKV0 = smb + K_STAGE_B;   // two KV stages follow Q

    const int tid  = threadIdx.x;
    const int wid  = tid >> 5;
    const int lane = tid & 31;
    const int g    = lane >> 2;
    const int qt   = blockIdx.x;
    const int bh   = blockIdx.y;
    const int h    = bh & 15;
    const int cbase = h * DHEAD;
    const int qrow0 = (bh >> 4) * TSEQ + qt * 128;

    // prologue: G0 = Q + KV0, G1 = KV1
    attn_load_q(sQ, bh, qt);
    attn_load_kv(sKV0, bh, 0);               // commits G0 (Q+KV0)
    attn_load_kv(sKV0 + KV_STAGE_B, bh, 1);  // commits G1

    float acc_o[8][4];
#pragma unroll
    for (int i = 0; i < 8; i++)
#pragma unroll
        for (int r = 0; r < 4; r++) acc_o[i][r] = 0.f;
    float m0 = -INFINITY, m1 = -INFINITY, l0 = 0.f, l1 = 0.f;

    for (int kt = 0; kt < 8; kt++) {
        if (kt < 7) CP_WAIT(1); else CP_WAIT(0);
        __syncthreads();

        const uint32_t sK = sKV0 + (kt & 1) * KV_STAGE_B;
        const uint32_t sV = sK + K_STAGE_B;

        // ---- S = Qh Kh^T : 4 k-steps ----
        float s_acc[16][4];
#pragma unroll
        for (int ni = 0; ni < 16; ni++)
#pragma unroll
            for (int r = 0; r < 4; r++) s_acc[ni][r] = 0.f;

#pragma unroll
        for (int ks = 0; ks < 4; ks++) {
            uint32_t a[4];
            LDSM_X4(a, sQ + ((wid * 16 + (lane & 15)) * QLD + ks * 16 + (lane >> 4) * 8) * 2);
            uint32_t bf[8][4];
            const int gg = lane >> 3;
#pragma unroll
            for (int np = 0; np < 8; np++) {
                const int row = np * 16 + (gg >> 1) * 8 + (lane & 7);
                LDSM_X4(bf[np], sK + (row * QLD + ks * 16 + (gg & 1) * 8) * 2);
            }
#pragma unroll
            for (int ni = 0; ni < 16; ni++)
                mma16816h(s_acc[ni], a, &bf[ni >> 1][(ni & 1) * 2]);
        }

        // ---- online softmax ----
        float rm0 = -INFINITY, rm1 = -INFINITY;
#pragma unroll
        for (int ni = 0; ni < 16; ni++) {
            s_acc[ni][0] *= 0.125f; s_acc[ni][1] *= 0.125f;
            s_acc[ni][2] *= 0.125f; s_acc[ni][3] *= 0.125f;
            rm0 = fmaxf(rm0, fmaxf(s_acc[ni][0], s_acc[ni][1]));
            rm1 = fmaxf(rm1, fmaxf(s_acc[ni][2], s_acc[ni][3]));
        }
        rm0 = fmaxf(rm0, __shfl_xor_sync(0xffffffffu, rm0, 1));
        rm0 = fmaxf(rm0, __shfl_xor_sync(0xffffffffu, rm0, 2));
        rm1 = fmaxf(rm1, __shfl_xor_sync(0xffffffffu, rm1, 1));
        rm1 = fmaxf(rm1, __shfl_xor_sync(0xffffffffu, rm1, 2));

        const float nm0 = fmaxf(m0, rm0);
        const float nm1 = fmaxf(m1, rm1);
        const float a0 = __expf(m0 - nm0);
        const float a1 = __expf(m1 - nm1);

        float rs0 = 0.f, rs1 = 0.f;
#pragma unroll
        for (int ni = 0; ni < 16; ni++) {
            s_acc[ni][0] = __expf(s_acc[ni][0] - nm0);
            s_acc[ni][1] = __expf(s_acc[ni][1] - nm0);
            s_acc[ni][2] = __expf(s_acc[ni][2] - nm1);
            s_acc[ni][3] = __expf(s_acc[ni][3] - nm1);
            rs0 += s_acc[ni][0] + s_acc[ni][1];
            rs1 += s_acc[ni][2] + s_acc[ni][3];
        }
        rs0 += __shfl_xor_sync(0xffffffffu, rs0, 1);
        rs0 += __shfl_xor_sync(0xffffffffu, rs0, 2);
        rs1 += __shfl_xor_sync(0xffffffffu, rs1, 1);
        rs1 += __shfl_xor_sync(0xffffffffu, rs1, 2);

        l0 = l0 * a0 + rs0;  m0 = nm0;
        l1 = l1 * a1 + rs1;  m1 = nm1;

#pragma unroll
        for (int ni = 0; ni < 8; ni++) {
            acc_o[ni][0] *= a0; acc_o[ni][1] *= a0;
            acc_o[ni][2] *= a1; acc_o[ni][3] *= a1;
        }

        // ---- O += P V ----
        const int gg = lane >> 3;
#pragma unroll
        for (int ks = 0; ks < 8; ks++) {
            uint32_t ph[4];
            {
                const float* t0 = s_acc[2 * ks];
                const float* t1 = s_acc[2 * ks + 1];
                ph[0] = packh2(t0[0], t0[1]);
                ph[1] = packh2(t0[2], t0[3]);
                ph[2] = packh2(t1[0], t1[1]);
                ph[3] = packh2(t1[2], t1[3]);
            }
            uint32_t vh[4][4];
#pragma unroll
            for (int np = 0; np < 4; np++) {
                const int row = np * 16 + (gg >> 1) * 8 + (lane & 7);
                const int col = ks * 16 + (gg & 1) * 8;
                LDSM_X4(vh[np], sV + (row * VLD + col) * 2);
            }
#pragma unroll
            for (int ni = 0; ni < 8; ni++)
                mma16816h(acc_o[ni], ph, &vh[ni >> 1][(ni & 1) * 2]);
        }

        // issue next-next KV after everyone is done with this stage's buffer
        __syncthreads();
        if (kt + 2 < 8)
            attn_load_kv(sKV0 + (kt & 1) * KV_STAGE_B, bh, kt + 2);
    }

    // ---- normalize and write fp16 g_As ----
    const float inv0 = 1.0f / l0;
    const float inv1 = 1.0f / l1;
    const int row0 = qrow0 + wid * 16 + g;
#pragma unroll
    for (int ni = 0; ni < 8; ni++) {
        const int col = cbase + ni * 8 + (lane & 3) * 2;
        *(__half2*)(g_As + (size_t)row0 * K_DIM + col) =
            __floats2half2_rn(acc_o[ni][0] * inv0, acc_o[ni][1] * inv0);
        *(__half2*)(g_As + (size_t)(row0 + 8) * K_DIM + col) =
            __floats2half2_rn(acc_o[ni][2] * inv1, acc_o[ni][3] * inv1);
    }
}

// ---------------------------------------------------------------------------
// kernel_launch
// ---------------------------------------------------------------------------
extern "C" void kernel_launch(void* const* d_in, const int* in_sizes, int n_in,
                              void* d_out, int out_size)
{
    const float* x  = (const float*)d_in[0];
    const float* Wq = (const float*)d_in[1];
    const float* Wk = (const float*)d_in[2];
    const float* Wv = (const float*)d_in[3];
    const float* Wo = (const float*)d_in[4];
    const float* bo = (const float*)d_in[5];
    float* out = (float*)d_out;

    cudaFuncSetAttribute(qkv_hmma_kernel, cudaFuncAttributeMaxDynamicSharedMemorySize, GEMM_SMEM);
    cudaFuncSetAttribute(out_hmma_kernel, cudaFuncAttributeMaxDynamicSharedMemorySize, GEMM_SMEM);
    cudaFuncSetAttribute(attn_hmma_kernel, cudaFuncAttributeMaxDynamicSharedMemorySize, ATTN_SMEM);

    // 1) input conversions
    {
        const int nx = M_ROWS * K_DIM / 4;
        conv_x_kernel<<<(nx + 255) / 256, 256>>>(x);
        const int nw = N_DIM * K_DIM / 4;
        conv_w_kernel<<<dim3((nw + 255) / 256, 1, 4), 256>>>(Wq, Wk, Wv, Wo);
    }

    // 2) QKV projections; Q'/K' written fp16 per-head directly, V fp32
    qkv_hmma_kernel<<<dim3(N_DIM / GBN, M_ROWS / GBM, 3), 256, GEMM_SMEM>>>();

    // 3) V transpose to fp16 per-head
    conv_vt_kernel<<<64 * 16, 256>>>();

    // 4) attention (single-product fp16, pipelined; writes fp16 g_As)
    attn_hmma_kernel<<<dim3(8, 64), 256, ATTN_SMEM>>>();

    // 5) output projection + bias
    out_hmma_kernel<<<dim3(N_DIM / GBN, M_ROWS / GBM), 256, GEMM_SMEM>>>(bo, out);
}

// round 13
// speedup vs baseline: 2.8403x; 1.0255x over previous
#include <cuda_runtime.h>
#include <cuda_bf16.h>
#include <cuda_fp16.h>
#include <math.h>
#include <stdint.h>
#include <string.h>

// ---------------------------------------------------------------------------
// Problem constants
// ---------------------------------------------------------------------------
#define M_ROWS 4096
#define K_DIM  1024
#define N_DIM  1024
#define HEADS  16
#define DHEAD  64
#define TSEQ   1024
#define BATCH  4

// fp16 scratch for projection GEMMs
__device__ __align__(16) __half g_xs[M_ROWS * K_DIM];
__device__ __align__(16) __half g_As[M_ROWS * K_DIM];
__device__ __align__(16) __half g_Ws[4 * N_DIM * K_DIM];

// attention fp16 operands, per-head [bh][t][64]
__device__ __align__(16) __half g_Qs2[64 * 1024 * 64];
__device__ __align__(16) __half g_Ks2[64 * 1024 * 64];
__device__ __align__(16) __half g_Vs[64 * 1024 * 64];

// ---------------------------------------------------------------------------
// PTX helpers
// ---------------------------------------------------------------------------
__device__ __forceinline__ uint32_t smem_u32(const void* p) {
    uint32_t a;
    asm("{ .reg .u64 t; cvta.to.shared.u64 t, %1; cvt.u32.u64 %0, t; }"
        : "=r"(a) : "l"(p));
    return a;
}
__device__ __forceinline__ void cp16(uint32_t s, const void* g) {
    asm volatile("cp.async.cg.shared.global [%0], [%1], 16;" :: "r"(s), "l"(g));
}
#define CP_COMMIT() asm volatile("cp.async.commit_group;" ::: "memory")
#define CP_WAIT(n)  asm volatile("cp.async.wait_group %0;" :: "n"(n) : "memory")

#define LDSM_X4(r, addr)                                                       \
    asm volatile("ldmatrix.sync.aligned.m8n8.x4.shared.b16 {%0,%1,%2,%3}, [%4];" \
                 : "=r"((r)[0]), "=r"((r)[1]), "=r"((r)[2]), "=r"((r)[3])      \
                 : "r"(addr))
#define LDSM_X4_T(r, addr)                                                     \
    asm volatile("ldmatrix.sync.aligned.m8n8.x4.trans.shared.b16 {%0,%1,%2,%3}, [%4];" \
                 : "=r"((r)[0]), "=r"((r)[1]), "=r"((r)[2]), "=r"((r)[3])      \
                 : "r"(addr))

__device__ __forceinline__ void mma16816h(float* c, const uint32_t* a,
                                          const uint32_t* b) {
    asm volatile(
        "mma.sync.aligned.m16n8k16.row.col.f32.f16.f16.f32 "
        "{%0,%1,%2,%3}, {%4,%5,%6,%7}, {%8,%9}, {%0,%1,%2,%3};"
        : "+f"(c[0]), "+f"(c[1]), "+f"(c[2]), "+f"(c[3])
        : "r"(a[0]), "r"(a[1]), "r"(a[2]), "r"(a[3]), "r"(b[0]), "r"(b[1]));
}

__device__ __forceinline__ uint32_t packh2(float x, float y) {
    __half2 t = __floats2half2_rn(x, y);
    uint32_t u;
    memcpy(&u, &t, 4);
    return u;
}

// ---------------------------------------------------------------------------
// HMMA fp16 NT GEMM: C = A[M,1024] @ B[N,1024]^T
// Store modes: 0 = fp32 C (+ optional bias); 1 = per-head fp16 [bh][t][64].
// ---------------------------------------------------------------------------
#define GBM 128
#define GBN 128
#define GBK 64
#define TILE_B  (128 * 128)
#define STAGE_B (2 * TILE_B)
#define NSTAGE  3
#define NCH     (K_DIM / GBK)            // 16
#define GEMM_SMEM (NSTAGE * STAGE_B)     // 98304

__device__ __forceinline__ uint32_t swz(uint32_t row, uint32_t seg) {
    return row * 128 + ((seg ^ (row & 7)) * 16);
}

__device__ __forceinline__ void load_chunk(const __half* __restrict__ A,
                                           const __half* __restrict__ B,
                                           int bm, int bn, int k0,
                                           uint32_t sA, uint32_t sB) {
    const int tid = threadIdx.x;
    const int row = tid >> 1;
    const int sb  = (tid & 1) * 4;
#pragma unroll
    for (int j = 0; j < 4; j++) {
        const int seg = sb + j;
        cp16(sA + swz(row, seg), A + (size_t)(bm + row) * K_DIM + k0 + seg * 8);
        cp16(sB + swz(row, seg), B + (size_t)(bn + row) * K_DIM + k0 + seg * 8);
    }
    CP_COMMIT();
}

template <int MODE>
__device__ void gemm_hmma_body(const __half* __restrict__ A,
                               const __half* __restrict__ B,
                               const float* __restrict__ bias,
                               float* __restrict__ C,
                               __half* __restrict__ Ch) {
    extern __shared__ char sm[];
    const uint32_t smb = smem_u32(sm);

    const int tid  = threadIdx.x;
    const int wid  = tid >> 5;
    const int lane = tid & 31;
    const int wm   = wid >> 2;
    const int wn   = wid & 3;
    const int bm   = blockIdx.y * GBM;
    const int bn   = blockIdx.x * GBN;

    float acc[4][4][4];
#pragma unroll
    for (int i = 0; i < 4; i++)
#pragma unroll
        for (int j = 0; j < 4; j++)
#pragma unroll
            for (int r = 0; r < 4; r++) acc[i][j][r] = 0.f;

#pragma unroll
    for (int s = 0; s < NSTAGE; s++)
        load_chunk(A, B, bm, bn, s * GBK,
                   smb + s * STAGE_B, smb + s * STAGE_B + TILE_B);

    for (int c = 0; c < NCH; c++) {
        const int rem = NCH - 1 - c;
        if (rem >= 2)      CP_WAIT(2);
        else if (rem == 1) CP_WAIT(1);
        else               CP_WAIT(0);
        __syncthreads();

        const uint32_t aB = smb + (c % NSTAGE) * STAGE_B;
        const uint32_t bB = aB + TILE_B;

#pragma unroll
        for (int ks = 0; ks < 4; ks++) {
            uint32_t afr[4][4];
#pragma unroll
            for (int mi = 0; mi < 4; mi++) {
                const int row = wm * 64 + mi * 16 + (lane & 15);
                const int seg = ks * 2 + (lane >> 4);
                LDSM_X4(afr[mi], aB + swz(row, seg));
            }
            uint32_t bfr[2][4];
            const int g = lane >> 3;
#pragma unroll
            for (int np = 0; np < 2; np++) {
                const int row = wn * 32 + np * 16 + (g >> 1) * 8 + (lane & 7);
                const int seg = ks * 2 + (g & 1);
                LDSM_X4(bfr[np], bB + swz(row, seg));
            }
#pragma unroll
            for (int mi = 0; mi < 4; mi++) {
#pragma unroll
                for (int ni = 0; ni < 4; ni++)
                    mma16816h(acc[mi][ni], afr[mi], &bfr[ni >> 1][(ni & 1) * 2]);
            }
        }
        __syncthreads();

        if (c + NSTAGE < NCH)
            load_chunk(A, B, bm, bn, (c + NSTAGE) * GBK,
                       smb + (c % NSTAGE) * STAGE_B,
                       smb + (c % NSTAGE) * STAGE_B + TILE_B);
    }

#pragma unroll
    for (int mi = 0; mi < 4; mi++) {
#pragma unroll
        for (int ni = 0; ni < 4; ni++) {
            const int r0 = bm + wm * 64 + mi * 16 + (lane >> 2);
            const int c0 = bn + wn * 32 + ni * 8 + (lane & 3) * 2;
            if (MODE == 0) {
                float2 v0 = make_float2(acc[mi][ni][0], acc[mi][ni][1]);
                float2 v1 = make_float2(acc[mi][ni][2], acc[mi][ni][3]);
                if (bias) {
                    const float b0 = bias[c0], b1 = bias[c0 + 1];
                    v0.x += b0; v0.y += b1;
                    v1.x += b0; v1.y += b1;
                }
                *(float2*)&C[(size_t)r0 * N_DIM + c0]       = v0;
                *(float2*)&C[(size_t)(r0 + 8) * N_DIM + c0] = v1;
            } else {
                // per-head fp16 layout: [b*16+h][t][64]
                const int b  = r0 >> 10;
                const int t  = r0 & 1023;
                const int h  = c0 >> 6;
                const int dd = c0 & 63;
                const size_t base = (((size_t)(b * 16 + h) * 1024 + t) << 6) + dd;
                *(__half2*)&Ch[base] =
                    __floats2half2_rn(acc[mi][ni][0], acc[mi][ni][1]);
                *(__half2*)&Ch[base + (8 << 6)] =
                    __floats2half2_rn(acc[mi][ni][2], acc[mi][ni][3]);
            }
        }
    }
}

__global__ __launch_bounds__(256, 2) void qkv_hmma_kernel() {
    const int z = blockIdx.z;
    __half* dst = (z == 0) ? g_Qs2 : (z == 1) ? g_Ks2 : g_Vs;
    gemm_hmma_body<1>(g_xs, g_Ws + (size_t)z * N_DIM * K_DIM, nullptr, nullptr, dst);
}

__global__ __launch_bounds__(256, 2) void out_hmma_kernel(const float* __restrict__ bo,
                                                          float* __restrict__ out) {
    gemm_hmma_body<0>(g_As, g_Ws + (size_t)3 * N_DIM * K_DIM, bo, out, nullptr);
}

// ---------------------------------------------------------------------------
// conversions (separate, correctly sized: x is 4x a weight matrix!)
// ---------------------------------------------------------------------------
__global__ void conv_x_kernel(const float* __restrict__ src) {
    const int i = blockIdx.x * blockDim.x + threadIdx.x;
    if (i >= M_ROWS * K_DIM / 4) return;
    float4 v = ((const float4*)src)[i];
    __half2* d = (__half2*)(g_xs) + i * 2;
    d[0] = __floats2half2_rn(v.x, v.y);
    d[1] = __floats2half2_rn(v.z, v.w);
}

__global__ void conv_w_kernel(const float* __restrict__ Wq, const float* __restrict__ Wk,
                              const float* __restrict__ Wv, const float* __restrict__ Wo) {
    const int z = blockIdx.z;
    const float* src = (z == 0) ? Wq : (z == 1) ? Wk : (z == 2) ? Wv : Wo;
    const int i = blockIdx.x * blockDim.x + threadIdx.x;
    if (i >= N_DIM * K_DIM / 4) return;
    float4 v = ((const float4*)src)[i];
    __half2* d = (__half2*)(g_Ws + (size_t)z * N_DIM * K_DIM) + i * 2;
    d[0] = __floats2half2_rn(v.x, v.y);
    d[1] = __floats2half2_rn(v.z, v.w);
}

// ---------------------------------------------------------------------------
// HMMA flash attention, single-product fp16:
//   S = Qh·Kh^T (4 k-steps);  O += Ph·Vh (8 k-steps, V via ldmatrix.trans)
// 2-stage K/V cp.async pipeline; smem padded to 116 KB -> 1 CTA/SM.
// Q/K/V smem: [128 rows][72 halves] (144B pitch).
// ---------------------------------------------------------------------------
#define QLD 72
#define T_STAGE_B (128 * QLD * 2)            // 18432
#define KV_STAGE_B (2 * T_STAGE_B)           // 36864
#define ATTN_SMEM 118784                     // pad to 116 KB: 1 CTA/SM

__device__ __forceinline__ void attn_load_tile(uint32_t s, const __half* g,
                                               int bh, int t0) {
    const int tid = threadIdx.x;
#pragma unroll
    for (int j = 0; j < 4; j++) {
        const int i = tid + j * 256;         // 0..1023
        const int r = i >> 3, sg = i & 7;
        cp16(s + (r * QLD + sg * 8) * 2,
             g + (((size_t)bh * 1024 + t0 + r) << 6) + sg * 8);
    }
}

__global__ __launch_bounds__(256, 1) void attn_hmma_kernel()
{
    extern __shared__ char sm[];
    const uint32_t smb = smem_u32(sm);
    const uint32_t sQ   = smb;
    const uint32_t sKV0 = smb + T_STAGE_B;

    const int tid  = threadIdx.x;
    const int wid  = tid >> 5;
    const int lane = tid & 31;
    const int g    = lane >> 2;
    const int qt   = blockIdx.x;
    const int bh   = blockIdx.y;
    const int h    = bh & 15;
    const int cbase = h * DHEAD;
    const int qrow0 = (bh >> 4) * TSEQ + qt * 128;

    // prologue: G0 = Q + KV0, G1 = KV1
    attn_load_tile(sQ, g_Qs2, bh, qt * 128);
    attn_load_tile(sKV0, g_Ks2, bh, 0);
    attn_load_tile(sKV0 + T_STAGE_B, g_Vs, bh, 0);
    CP_COMMIT();
    attn_load_tile(sKV0 + KV_STAGE_B, g_Ks2, bh, 128);
    attn_load_tile(sKV0 + KV_STAGE_B + T_STAGE_B, g_Vs, bh, 128);
    CP_COMMIT();

    float acc_o[8][4];
#pragma unroll
    for (int i = 0; i < 8; i++)
#pragma unroll
        for (int r = 0; r < 4; r++) acc_o[i][r] = 0.f;
    float m0 = -INFINITY, m1 = -INFINITY, l0 = 0.f, l1 = 0.f;

    for (int kt = 0; kt < 8; kt++) {
        if (kt < 7) CP_WAIT(1); else CP_WAIT(0);
        __syncthreads();

        const uint32_t sK = sKV0 + (kt & 1) * KV_STAGE_B;
        const uint32_t sV = sK + T_STAGE_B;

        // ---- S = Qh Kh^T : 4 k-steps ----
        float s_acc[16][4];
#pragma unroll
        for (int ni = 0; ni < 16; ni++)
#pragma unroll
            for (int r = 0; r < 4; r++) s_acc[ni][r] = 0.f;

#pragma unroll
        for (int ks = 0; ks < 4; ks++) {
            uint32_t a[4];
            LDSM_X4(a, sQ + ((wid * 16 + (lane & 15)) * QLD + ks * 16 + (lane >> 4) * 8) * 2);
            uint32_t bf[8][4];
            const int gg = lane >> 3;
#pragma unroll
            for (int np = 0; np < 8; np++) {
                const int row = np * 16 + (gg >> 1) * 8 + (lane & 7);
                LDSM_X4(bf[np], sK + (row * QLD + ks * 16 + (gg & 1) * 8) * 2);
            }
#pragma unroll
            for (int ni = 0; ni < 16; ni++)
                mma16816h(s_acc[ni], a, &bf[ni >> 1][(ni & 1) * 2]);
        }

        // ---- online softmax ----
        float rm0 = -INFINITY, rm1 = -INFINITY;
#pragma unroll
        for (int ni = 0; ni < 16; ni++) {
            s_acc[ni][0] *= 0.125f; s_acc[ni][1] *= 0.125f;
            s_acc[ni][2] *= 0.125f; s_acc[ni][3] *= 0.125f;
            rm0 = fmaxf(rm0, fmaxf(s_acc[ni][0], s_acc[ni][1]));
            rm1 = fmaxf(rm1, fmaxf(s_acc[ni][2], s_acc[ni][3]));
        }
        rm0 = fmaxf(rm0, __shfl_xor_sync(0xffffffffu, rm0, 1));
        rm0 = fmaxf(rm0, __shfl_xor_sync(0xffffffffu, rm0, 2));
        rm1 = fmaxf(rm1, __shfl_xor_sync(0xffffffffu, rm1, 1));
        rm1 = fmaxf(rm1, __shfl_xor_sync(0xffffffffu, rm1, 2));

        const float nm0 = fmaxf(m0, rm0);
        const float nm1 = fmaxf(m1, rm1);
        const float a0 = __expf(m0 - nm0);
        const float a1 = __expf(m1 - nm1);

        float rs0 = 0.f, rs1 = 0.f;
#pragma unroll
        for (int ni = 0; ni < 16; ni++) {
            s_acc[ni][0] = __expf(s_acc[ni][0] - nm0);
            s_acc[ni][1] = __expf(s_acc[ni][1] - nm0);
            s_acc[ni][2] = __expf(s_acc[ni][2] - nm1);
            s_acc[ni][3] = __expf(s_acc[ni][3] - nm1);
            rs0 += s_acc[ni][0] + s_acc[ni][1];
            rs1 += s_acc[ni][2] + s_acc[ni][3];
        }
        rs0 += __shfl_xor_sync(0xffffffffu, rs0, 1);
        rs0 += __shfl_xor_sync(0xffffffffu, rs0, 2);
        rs1 += __shfl_xor_sync(0xffffffffu, rs1, 1);
        rs1 += __shfl_xor_sync(0xffffffffu, rs1, 2);

        l0 = l0 * a0 + rs0;  m0 = nm0;
        l1 = l1 * a1 + rs1;  m1 = nm1;

#pragma unroll
        for (int ni = 0; ni < 8; ni++) {
            acc_o[ni][0] *= a0; acc_o[ni][1] *= a0;
            acc_o[ni][2] *= a1; acc_o[ni][3] *= a1;
        }

        // ---- O += P V : V fragments via ldmatrix.trans from [t][d] smem ----
        const int gg = lane >> 3;
#pragma unroll
        for (int ks = 0; ks < 8; ks++) {          // t 16-blocks
            uint32_t ph[4];
            {
                const float* t0 = s_acc[2 * ks];
                const float* t1 = s_acc[2 * ks + 1];
                ph[0] = packh2(t0[0], t0[1]);
                ph[1] = packh2(t0[2], t0[3]);
                ph[2] = packh2(t1[0], t1[1]);
                ph[3] = packh2(t1[2], t1[3]);
            }
            uint32_t vh[4][4];
#pragma unroll
            for (int np = 0; np < 4; np++) {      // d 16-blocks
                const int row_t = ks * 16 + (gg & 1) * 8 + (lane & 7);
                const int col_d = np * 16 + (gg >> 1) * 8;
                LDSM_X4_T(vh[np], sV + (row_t * QLD + col_d) * 2);
            }
#pragma unroll
            for (int ni = 0; ni < 8; ni++)
                mma16816h(acc_o[ni], ph, &vh[ni >> 1][(ni & 1) * 2]);
        }

        // issue next-next KV after everyone is done with this stage's buffer
        __syncthreads();
        if (kt + 2 < 8) {
            const uint32_t sDst = sKV0 + (kt & 1) * KV_STAGE_B;
            attn_load_tile(sDst, g_Ks2, bh, (kt + 2) * 128);
            attn_load_tile(sDst + T_STAGE_B, g_Vs, bh, (kt + 2) * 128);
            CP_COMMIT();
        }
    }

    // ---- normalize and write fp16 g_As ----
    const float inv0 = 1.0f / l0;
    const float inv1 = 1.0f / l1;
    const int row0 = qrow0 + wid * 16 + g;
#pragma unroll
    for (int ni = 0; ni < 8; ni++) {
        const int col = cbase + ni * 8 + (lane & 3) * 2;
        *(__half2*)(g_As + (size_t)row0 * K_DIM + col) =
            __floats2half2_rn(acc_o[ni][0] * inv0, acc_o[ni][1] * inv0);
        *(__half2*)(g_As + (size_t)(row0 + 8) * K_DIM + col) =
            __floats2half2_rn(acc_o[ni][2] * inv1, acc_o[ni][3] * inv1);
    }
}

// ---------------------------------------------------------------------------
// kernel_launch
// ---------------------------------------------------------------------------
extern "C" void kernel_launch(void* const* d_in, const int* in_sizes, int n_in,
                              void* d_out, int out_size)
{
    const float* x  = (const float*)d_in[0];
    const float* Wq = (const float*)d_in[1];
    const float* Wk = (const float*)d_in[2];
    const float* Wv = (const float*)d_in[3];
    const float* Wo = (const float*)d_in[4];
    const float* bo = (const float*)d_in[5];
    float* out = (float*)d_out;

    cudaFuncSetAttribute(qkv_hmma_kernel, cudaFuncAttributeMaxDynamicSharedMemorySize, GEMM_SMEM);
    cudaFuncSetAttribute(out_hmma_kernel, cudaFuncAttributeMaxDynamicSharedMemorySize, GEMM_SMEM);
    cudaFuncSetAttribute(attn_hmma_kernel, cudaFuncAttributeMaxDynamicSharedMemorySize, ATTN_SMEM);

    // 1) fp32 -> fp16 conversions (x is 4M elements, W are 1M each)
    {
        const int nx = M_ROWS * K_DIM / 4;
        conv_x_kernel<<<(nx + 255) / 256, 256>>>(x);
        const int nw = N_DIM * K_DIM / 4;
        conv_w_kernel<<<dim3((nw + 255) / 256, 1, 4), 256>>>(Wq, Wk, Wv, Wo);
    }

    // 2) QKV projections; Q'/K'/V' written fp16 per-head directly
    qkv_hmma_kernel<<<dim3(N_DIM / GBN, M_ROWS / GBM, 3), 256, GEMM_SMEM>>>();

    // 3) attention (single-product fp16, pipelined, trans-ldmatrix V)
    attn_hmma_kernel<<<dim3(8, 64), 256, ATTN_SMEM>>>();

    // 4) output projection + bias
    out_hmma_kernel<<<dim3(N_DIM / GBN, M_ROWS / GBM), 256, GEMM_SMEM>>>(bo, out);
}

// round 14
// speedup vs baseline: 2.8711x; 1.0109x over previous
#include <cuda_runtime.h>
#include <cuda_bf16.h>
#include <cuda_fp16.h>
#include <math.h>
#include <stdint.h>
#include <string.h>

// ---------------------------------------------------------------------------
// Problem constants
// ---------------------------------------------------------------------------
#define M_ROWS 4096
#define K_DIM  1024
#define N_DIM  1024
#define HEADS  16
#define DHEAD  64
#define TSEQ   1024
#define BATCH  4

// fp16 scratch for projection GEMMs
__device__ __align__(16) __half g_xs[M_ROWS * K_DIM];
__device__ __align__(16) __half g_As[M_ROWS * K_DIM];
__device__ __align__(16) __half g_Ws[4 * N_DIM * K_DIM];

// attention fp16 operands, per-head [bh][t][64]
__device__ __align__(16) __half g_Qs2[64 * 1024 * 64];
__device__ __align__(16) __half g_Ks2[64 * 1024 * 64];
__device__ __align__(16) __half g_Vs[64 * 1024 * 64];

// ---------------------------------------------------------------------------
// PTX helpers
// ---------------------------------------------------------------------------
__device__ __forceinline__ uint32_t smem_u32(const void* p) {
    uint32_t a;
    asm("{ .reg .u64 t; cvta.to.shared.u64 t, %1; cvt.u32.u64 %0, t; }"
        : "=r"(a) : "l"(p));
    return a;
}
__device__ __forceinline__ void cp16(uint32_t s, const void* g) {
    asm volatile("cp.async.cg.shared.global [%0], [%1], 16;" :: "r"(s), "l"(g));
}
#define CP_COMMIT() asm volatile("cp.async.commit_group;" ::: "memory")
#define CP_WAIT(n)  asm volatile("cp.async.wait_group %0;" :: "n"(n) : "memory")

#define LDSM_X4(r, addr)                                                       \
    asm volatile("ldmatrix.sync.aligned.m8n8.x4.shared.b16 {%0,%1,%2,%3}, [%4];" \
                 : "=r"((r)[0]), "=r"((r)[1]), "=r"((r)[2]), "=r"((r)[3])      \
                 : "r"(addr))
#define LDSM_X4_T(r, addr)                                                     \
    asm volatile("ldmatrix.sync.aligned.m8n8.x4.trans.shared.b16 {%0,%1,%2,%3}, [%4];" \
                 : "=r"((r)[0]), "=r"((r)[1]), "=r"((r)[2]), "=r"((r)[3])      \
                 : "r"(addr))

__device__ __forceinline__ void mma16816h(float* c, const uint32_t* a,
                                          const uint32_t* b) {
    asm volatile(
        "mma.sync.aligned.m16n8k16.row.col.f32.f16.f16.f32 "
        "{%0,%1,%2,%3}, {%4,%5,%6,%7}, {%8,%9}, {%0,%1,%2,%3};"
        : "+f"(c[0]), "+f"(c[1]), "+f"(c[2]), "+f"(c[3])
        : "r"(a[0]), "r"(a[1]), "r"(a[2]), "r"(a[3]), "r"(b[0]), "r"(b[1]));
}

__device__ __forceinline__ uint32_t packh2(float x, float y) {
    __half2 t = __floats2half2_rn(x, y);
    uint32_t u;
    memcpy(&u, &t, 4);
    return u;
}

// ---------------------------------------------------------------------------
// HMMA fp16 NT GEMM (validated; unchanged)
// ---------------------------------------------------------------------------
#define GBM 128
#define GBN 128
#define GBK 64
#define TILE_B  (128 * 128)
#define STAGE_B (2 * TILE_B)
#define NSTAGE  3
#define NCH     (K_DIM / GBK)            // 16
#define GEMM_SMEM (NSTAGE * STAGE_B)     // 98304

__device__ __forceinline__ uint32_t swz(uint32_t row, uint32_t seg) {
    return row * 128 + ((seg ^ (row & 7)) * 16);
}

__device__ __forceinline__ void load_chunk(const __half* __restrict__ A,
                                           const __half* __restrict__ B,
                                           int bm, int bn, int k0,
                                           uint32_t sA, uint32_t sB) {
    const int tid = threadIdx.x;
    const int row = tid >> 1;
    const int sb  = (tid & 1) * 4;
#pragma unroll
    for (int j = 0; j < 4; j++) {
        const int seg = sb + j;
        cp16(sA + swz(row, seg), A + (size_t)(bm + row) * K_DIM + k0 + seg * 8);
        cp16(sB + swz(row, seg), B + (size_t)(bn + row) * K_DIM + k0 + seg * 8);
    }
    CP_COMMIT();
}

template <int MODE>
__device__ void gemm_hmma_body(const __half* __restrict__ A,
                               const __half* __restrict__ B,
                               const float* __restrict__ bias,
                               float* __restrict__ C,
                               __half* __restrict__ Ch) {
    extern __shared__ char sm[];
    const uint32_t smb = smem_u32(sm);

    const int tid  = threadIdx.x;
    const int wid  = tid >> 5;
    const int lane = tid & 31;
    const int wm   = wid >> 2;
    const int wn   = wid & 3;
    const int bm   = blockIdx.y * GBM;
    const int bn   = blockIdx.x * GBN;

    float acc[4][4][4];
#pragma unroll
    for (int i = 0; i < 4; i++)
#pragma unroll
        for (int j = 0; j < 4; j++)
#pragma unroll
            for (int r = 0; r < 4; r++) acc[i][j][r] = 0.f;

#pragma unroll
    for (int s = 0; s < NSTAGE; s++)
        load_chunk(A, B, bm, bn, s * GBK,
                   smb + s * STAGE_B, smb + s * STAGE_B + TILE_B);

    for (int c = 0; c < NCH; c++) {
        const int rem = NCH - 1 - c;
        if (rem >= 2)      CP_WAIT(2);
        else if (rem == 1) CP_WAIT(1);
        else               CP_WAIT(0);
        __syncthreads();

        const uint32_t aB = smb + (c % NSTAGE) * STAGE_B;
        const uint32_t bB = aB + TILE_B;

#pragma unroll
        for (int ks = 0; ks < 4; ks++) {
            uint32_t afr[4][4];
#pragma unroll
            for (int mi = 0; mi < 4; mi++) {
                const int row = wm * 64 + mi * 16 + (lane & 15);
                const int seg = ks * 2 + (lane >> 4);
                LDSM_X4(afr[mi], aB + swz(row, seg));
            }
            uint32_t bfr[2][4];
            const int g = lane >> 3;
#pragma unroll
            for (int np = 0; np < 2; np++) {
                const int row = wn * 32 + np * 16 + (g >> 1) * 8 + (lane & 7);
                const int seg = ks * 2 + (g & 1);
                LDSM_X4(bfr[np], bB + swz(row, seg));
            }
#pragma unroll
            for (int mi = 0; mi < 4; mi++) {
#pragma unroll
                for (int ni = 0; ni < 4; ni++)
                    mma16816h(acc[mi][ni], afr[mi], &bfr[ni >> 1][(ni & 1) * 2]);
            }
        }
        __syncthreads();

        if (c + NSTAGE < NCH)
            load_chunk(A, B, bm, bn, (c + NSTAGE) * GBK,
                       smb + (c % NSTAGE) * STAGE_B,
                       smb + (c % NSTAGE) * STAGE_B + TILE_B);
    }

#pragma unroll
    for (int mi = 0; mi < 4; mi++) {
#pragma unroll
        for (int ni = 0; ni < 4; ni++) {
            const int r0 = bm + wm * 64 + mi * 16 + (lane >> 2);
            const int c0 = bn + wn * 32 + ni * 8 + (lane & 3) * 2;
            if (MODE == 0) {
                float2 v0 = make_float2(acc[mi][ni][0], acc[mi][ni][1]);
                float2 v1 = make_float2(acc[mi][ni][2], acc[mi][ni][3]);
                if (bias) {
                    const float b0 = bias[c0], b1 = bias[c0 + 1];
                    v0.x += b0; v0.y += b1;
                    v1.x += b0; v1.y += b1;
                }
                *(float2*)&C[(size_t)r0 * N_DIM + c0]       = v0;
                *(float2*)&C[(size_t)(r0 + 8) * N_DIM + c0] = v1;
            } else {
                const int b  = r0 >> 10;
                const int t  = r0 & 1023;
                const int h  = c0 >> 6;
                const int dd = c0 & 63;
                const size_t base = (((size_t)(b * 16 + h) * 1024 + t) << 6) + dd;
                *(__half2*)&Ch[base] =
                    __floats2half2_rn(acc[mi][ni][0], acc[mi][ni][1]);
                *(__half2*)&Ch[base + (8 << 6)] =
                    __floats2half2_rn(acc[mi][ni][2], acc[mi][ni][3]);
            }
        }
    }
}

__global__ __launch_bounds__(256, 2) void qkv_hmma_kernel() {
    const int z = blockIdx.z;
    __half* dst = (z == 0) ? g_Qs2 : (z == 1) ? g_Ks2 : g_Vs;
    gemm_hmma_body<1>(g_xs, g_Ws + (size_t)z * N_DIM * K_DIM, nullptr, nullptr, dst);
}

__global__ __launch_bounds__(256, 2) void out_hmma_kernel(const float* __restrict__ bo,
                                                          float* __restrict__ out) {
    gemm_hmma_body<0>(g_As, g_Ws + (size_t)3 * N_DIM * K_DIM, bo, out, nullptr);
}

// ---------------------------------------------------------------------------
// conversions
// ---------------------------------------------------------------------------
__global__ void conv_x_kernel(const float* __restrict__ src) {
    const int i = blockIdx.x * blockDim.x + threadIdx.x;
    if (i >= M_ROWS * K_DIM / 4) return;
    float4 v = ((const float4*)src)[i];
    __half2* d = (__half2*)(g_xs) + i * 2;
    d[0] = __floats2half2_rn(v.x, v.y);
    d[1] = __floats2half2_rn(v.z, v.w);
}

__global__ void conv_w_kernel(const float* __restrict__ Wq, const float* __restrict__ Wk,
                              const float* __restrict__ Wv, const float* __restrict__ Wo) {
    const int z = blockIdx.z;
    const float* src = (z == 0) ? Wq : (z == 1) ? Wk : (z == 2) ? Wv : Wo;
    const int i = blockIdx.x * blockDim.x + threadIdx.x;
    if (i >= N_DIM * K_DIM / 4) return;
    float4 v = ((const float4*)src)[i];
    __half2* d = (__half2*)(g_Ws + (size_t)z * N_DIM * K_DIM) + i * 2;
    d[0] = __floats2half2_rn(v.x, v.y);
    d[1] = __floats2half2_rn(v.z, v.w);
}

// ---------------------------------------------------------------------------
// HMMA flash attention v2: 512 threads (16 warps = 4/SMSP), q-tile 256,
// KV tile 64 keys, 16 kt iterations, 2-stage cp.async pipeline.
// Each warp owns 16 q-rows; s_acc[8][4] (64 keys) keeps regs <= 128.
// ---------------------------------------------------------------------------
#define QLD 72
#define AQ_BYTES (256 * QLD * 2)             // 36864
#define AK_BYTES (64 * QLD * 2)              // 9216 (K tile)
#define KV_STAGE_B (2 * AK_BYTES)            // 18432 (K + V)
#define ATTN_SMEM (AQ_BYTES + 2 * KV_STAGE_B) // 73728

__device__ __forceinline__ void attn_load_q256(uint32_t sQ, int bh, int t0) {
    const int tid = threadIdx.x;
#pragma unroll
    for (int j = 0; j < 4; j++) {
        const int i = tid + j * 512;         // 0..2047
        const int r = i >> 3, sg = i & 7;
        cp16(sQ + (r * QLD + sg * 8) * 2,
             g_Qs2 + (((size_t)bh * 1024 + t0 + r) << 6) + sg * 8);
    }
}
__device__ __forceinline__ void attn_load_kv64(uint32_t sKV, int bh, int t0) {
    const int tid = threadIdx.x;                  // 512 = 64 rows x 8 segs
    const int r = tid >> 3, sg = tid & 7;
    cp16(sKV + (r * QLD + sg * 8) * 2,
         g_Ks2 + (((size_t)bh * 1024 + t0 + r) << 6) + sg * 8);
    cp16(sKV + AK_BYTES + (r * QLD + sg * 8) * 2,
         g_Vs + (((size_t)bh * 1024 + t0 + r) << 6) + sg * 8);
    CP_COMMIT();
}

__global__ __launch_bounds__(512, 1) void attn_hmma_kernel()
{
    extern __shared__ char sm[];
    const uint32_t smb = smem_u32(sm);
    const uint32_t sQ   = smb;
    const uint32_t sKV0 = smb + AQ_BYTES;

    const int tid  = threadIdx.x;
    const int wid  = tid >> 5;               // 0..15
    const int lane = tid & 31;
    const int g    = lane >> 2;
    const int qt   = blockIdx.x;             // 0..3
    const int bh   = blockIdx.y;
    const int h    = bh & 15;
    const int cbase = h * DHEAD;
    const int qrow0 = (bh >> 4) * TSEQ + qt * 256;

    attn_load_q256(sQ, bh, qt * 256);
    attn_load_kv64(sKV0, bh, 0);
    attn_load_kv64(sKV0 + KV_STAGE_B, bh, 64);

    float acc_o[8][4];
#pragma unroll
    for (int i = 0; i < 8; i++)
#pragma unroll
        for (int r = 0; r < 4; r++) acc_o[i][r] = 0.f;
    float m0 = -INFINITY, m1 = -INFINITY, l0 = 0.f, l1 = 0.f;

    for (int kt = 0; kt < 16; kt++) {
        if (kt < 15) CP_WAIT(1); else CP_WAIT(0);
        __syncthreads();

        const uint32_t sK = sKV0 + (kt & 1) * KV_STAGE_B;
        const uint32_t sV = sK + AK_BYTES;

        // ---- S = Qh Kh^T : 16 q-rows x 64 keys ----
        float s_acc[8][4];
#pragma unroll
        for (int ni = 0; ni < 8; ni++)
#pragma unroll
            for (int r = 0; r < 4; r++) s_acc[ni][r] = 0.f;

        const int gg = lane >> 3;
#pragma unroll
        for (int ks = 0; ks < 4; ks++) {
            uint32_t a[4];
            LDSM_X4(a, sQ + ((wid * 16 + (lane & 15)) * QLD + ks * 16 + (lane >> 4) * 8) * 2);
            uint32_t bf[4][4];
#pragma unroll
            for (int np = 0; np < 4; np++) {
                const int row = np * 16 + (gg >> 1) * 8 + (lane & 7);
                LDSM_X4(bf[np], sK + (row * QLD + ks * 16 + (gg & 1) * 8) * 2);
            }
#pragma unroll
            for (int ni = 0; ni < 8; ni++)
                mma16816h(s_acc[ni], a, &bf[ni >> 1][(ni & 1) * 2]);
        }

        // ---- online softmax (64-key tile) ----
        float rm0 = -INFINITY, rm1 = -INFINITY;
#pragma unroll
        for (int ni = 0; ni < 8; ni++) {
            s_acc[ni][0] *= 0.125f; s_acc[ni][1] *= 0.125f;
            s_acc[ni][2] *= 0.125f; s_acc[ni][3] *= 0.125f;
            rm0 = fmaxf(rm0, fmaxf(s_acc[ni][0], s_acc[ni][1]));
            rm1 = fmaxf(rm1, fmaxf(s_acc[ni][2], s_acc[ni][3]));
        }
        rm0 = fmaxf(rm0, __shfl_xor_sync(0xffffffffu, rm0, 1));
        rm0 = fmaxf(rm0, __shfl_xor_sync(0xffffffffu, rm0, 2));
        rm1 = fmaxf(rm1, __shfl_xor_sync(0xffffffffu, rm1, 1));
        rm1 = fmaxf(rm1, __shfl_xor_sync(0xffffffffu, rm1, 2));

        const float nm0 = fmaxf(m0, rm0);
        const float nm1 = fmaxf(m1, rm1);
        const float a0 = __expf(m0 - nm0);
        const float a1 = __expf(m1 - nm1);

        float rs0 = 0.f, rs1 = 0.f;
#pragma unroll
        for (int ni = 0; ni < 8; ni++) {
            s_acc[ni][0] = __expf(s_acc[ni][0] - nm0);
            s_acc[ni][1] = __expf(s_acc[ni][1] - nm0);
            s_acc[ni][2] = __expf(s_acc[ni][2] - nm1);
            s_acc[ni][3] = __expf(s_acc[ni][3] - nm1);
            rs0 += s_acc[ni][0] + s_acc[ni][1];
            rs1 += s_acc[ni][2] + s_acc[ni][3];
        }
        rs0 += __shfl_xor_sync(0xffffffffu, rs0, 1);
        rs0 += __shfl_xor_sync(0xffffffffu, rs0, 2);
        rs1 += __shfl_xor_sync(0xffffffffu, rs1, 1);
        rs1 += __shfl_xor_sync(0xffffffffu, rs1, 2);

        l0 = l0 * a0 + rs0;  m0 = nm0;
        l1 = l1 * a1 + rs1;  m1 = nm1;

#pragma unroll
        for (int ni = 0; ni < 8; ni++) {
            acc_o[ni][0] *= a0; acc_o[ni][1] *= a0;
            acc_o[ni][2] *= a1; acc_o[ni][3] *= a1;
        }

        // ---- O += P V : V via ldmatrix.trans, 4 t-blocks x 4 d-blocks ----
#pragma unroll
        for (int ks = 0; ks < 4; ks++) {          // t 16-blocks of the 64 keys
            uint32_t ph[4];
            {
                const float* t0 = s_acc[2 * ks];
                const float* t1 = s_acc[2 * ks + 1];
                ph[0] = packh2(t0[0], t0[1]);
                ph[1] = packh2(t0[2], t0[3]);
                ph[2] = packh2(t1[0], t1[1]);
                ph[3] = packh2(t1[2], t1[3]);
            }
            uint32_t vh[4][4];
#pragma unroll
            for (int np = 0; np < 4; np++) {      // d 16-blocks
                const int row_t = ks * 16 + (gg & 1) * 8 + (lane & 7);
                const int col_d = np * 16 + (gg >> 1) * 8;
                LDSM_X4_T(vh[np], sV + (row_t * QLD + col_d) * 2);
            }
#pragma unroll
            for (int ni = 0; ni < 8; ni++)
                mma16816h(acc_o[ni], ph, &vh[ni >> 1][(ni & 1) * 2]);
        }

        __syncthreads();
        if (kt + 2 < 16)
            attn_load_kv64(sKV0 + (kt & 1) * KV_STAGE_B, bh, (kt + 2) * 64);
    }

    // ---- normalize and write fp16 g_As ----
    const float inv0 = 1.0f / l0;
    const float inv1 = 1.0f / l1;
    const int row0 = qrow0 + wid * 16 + g;
#pragma unroll
    for (int ni = 0; ni < 8; ni++) {
        const int col = cbase + ni * 8 + (lane & 3) * 2;
        *(__half2*)(g_As + (size_t)row0 * K_DIM + col) =
            __floats2half2_rn(acc_o[ni][0] * inv0, acc_o[ni][1] * inv0);
        *(__half2*)(g_As + (size_t)(row0 + 8) * K_DIM + col) =
            __floats2half2_rn(acc_o[ni][2] * inv1, acc_o[ni][3] * inv1);
    }
}

// ---------------------------------------------------------------------------
// kernel_launch
// ---------------------------------------------------------------------------
extern "C" void kernel_launch(void* const* d_in, const int* in_sizes, int n_in,
                              void* d_out, int out_size)
{
    const float* x  = (const float*)d_in[0];
    const float* Wq = (const float*)d_in[1];
    const float* Wk = (const float*)d_in[2];
    const float* Wv = (const float*)d_in[3];
    const float* Wo = (const float*)d_in[4];
    const float* bo = (const float*)d_in[5];
    float* out = (float*)d_out;

    cudaFuncSetAttribute(qkv_hmma_kernel, cudaFuncAttributeMaxDynamicSharedMemorySize, GEMM_SMEM);
    cudaFuncSetAttribute(out_hmma_kernel, cudaFuncAttributeMaxDynamicSharedMemorySize, GEMM_SMEM);
    cudaFuncSetAttribute(attn_hmma_kernel, cudaFuncAttributeMaxDynamicSharedMemorySize, ATTN_SMEM);

    // 1) fp32 -> fp16 conversions
    {
        const int nx = M_ROWS * K_DIM / 4;
        conv_x_kernel<<<(nx + 255) / 256, 256>>>(x);
        const int nw = N_DIM * K_DIM / 4;
        conv_w_kernel<<<dim3((nw + 255) / 256, 1, 4), 256>>>(Wq, Wk, Wv, Wo);
    }

    // 2) QKV projections; Q'/K'/V' written fp16 per-head directly
    qkv_hmma_kernel<<<dim3(N_DIM / GBN, M_ROWS / GBM, 3), 256, GEMM_SMEM>>>();

    // 3) attention (512 threads, q-tile 256, 64-key KV tiles)
    attn_hmma_kernel<<<dim3(4, 64), 512, ATTN_SMEM>>>();

    // 4) output projection + bias
    out_hmma_kernel<<<dim3(N_DIM / GBN, M_ROWS / GBM), 256, GEMM_SMEM>>>(bo, out);
}

// round 15
// speedup vs baseline: 3.0381x; 1.0582x over previous
#include <cuda_runtime.h>
#include <cuda_bf16.h>
#include <cuda_fp16.h>
#include <math.h>
#include <stdint.h>
#include <string.h>

// ---------------------------------------------------------------------------
// Problem constants
// ---------------------------------------------------------------------------
#define M_ROWS 4096
#define K_DIM  1024
#define N_DIM  1024
#define HEADS  16
#define DHEAD  64
#define TSEQ   1024
#define BATCH  4

// Q pre-scale: 1/sqrt(64) * log2(e) so softmax exp becomes bare exp2
#define QSCALE 0.1803368801111137f

// fp16 scratch for projection GEMMs
__device__ __align__(16) __half g_xs[M_ROWS * K_DIM];
__device__ __align__(16) __half g_As[M_ROWS * K_DIM];
__device__ __align__(16) __half g_Ws[4 * N_DIM * K_DIM];

// attention fp16 operands, per-head [bh][t][64]
__device__ __align__(16) __half g_Qs2[64 * 1024 * 64];
__device__ __align__(16) __half g_Ks2[64 * 1024 * 64];
__device__ __align__(16) __half g_Vs[64 * 1024 * 64];

// ---------------------------------------------------------------------------
// PTX helpers
// ---------------------------------------------------------------------------
__device__ __forceinline__ uint32_t smem_u32(const void* p) {
    uint32_t a;
    asm("{ .reg .u64 t; cvta.to.shared.u64 t, %1; cvt.u32.u64 %0, t; }"
        : "=r"(a) : "l"(p));
    return a;
}
__device__ __forceinline__ void cp16(uint32_t s, const void* g) {
    asm volatile("cp.async.cg.shared.global [%0], [%1], 16;" :: "r"(s), "l"(g));
}
#define CP_COMMIT() asm volatile("cp.async.commit_group;" ::: "memory")
#define CP_WAIT(n)  asm volatile("cp.async.wait_group %0;" :: "n"(n) : "memory")

#define LDSM_X4(r, addr)                                                       \
    asm volatile("ldmatrix.sync.aligned.m8n8.x4.shared.b16 {%0,%1,%2,%3}, [%4];" \
                 : "=r"((r)[0]), "=r"((r)[1]), "=r"((r)[2]), "=r"((r)[3])      \
                 : "r"(addr))
#define LDSM_X4_T(r, addr)                                                     \
    asm volatile("ldmatrix.sync.aligned.m8n8.x4.trans.shared.b16 {%0,%1,%2,%3}, [%4];" \
                 : "=r"((r)[0]), "=r"((r)[1]), "=r"((r)[2]), "=r"((r)[3])      \
                 : "r"(addr))

__device__ __forceinline__ void mma16816h(float* c, const uint32_t* a,
                                          const uint32_t* b) {
    asm volatile(
        "mma.sync.aligned.m16n8k16.row.col.f32.f16.f16.f32 "
        "{%0,%1,%2,%3}, {%4,%5,%6,%7}, {%8,%9}, {%0,%1,%2,%3};"
        : "+f"(c[0]), "+f"(c[1]), "+f"(c[2]), "+f"(c[3])
        : "r"(a[0]), "r"(a[1]), "r"(a[2]), "r"(a[3]), "r"(b[0]), "r"(b[1]));
}

__device__ __forceinline__ uint32_t packh2(float x, float y) {
    __half2 t = __floats2half2_rn(x, y);
    uint32_t u;
    memcpy(&u, &t, 4);
    return u;
}

// ---------------------------------------------------------------------------
// HMMA fp16 NT GEMM (validated). MODE 0 = fp32 C (+bias); MODE 1 = per-head
// fp16 [bh][t][64], output scaled by `oscale`.
// ---------------------------------------------------------------------------
#define GBM 128
#define GBN 128
#define GBK 64
#define TILE_B  (128 * 128)
#define STAGE_B (2 * TILE_B)
#define NSTAGE  3
#define NCH     (K_DIM / GBK)            // 16
#define GEMM_SMEM (NSTAGE * STAGE_B)     // 98304

__device__ __forceinline__ uint32_t swz(uint32_t row, uint32_t seg) {
    return row * 128 + ((seg ^ (row & 7)) * 16);
}

__device__ __forceinline__ void load_chunk(const __half* __restrict__ A,
                                           const __half* __restrict__ B,
                                           int bm, int bn, int k0,
                                           uint32_t sA, uint32_t sB) {
    const int tid = threadIdx.x;
    const int row = tid >> 1;
    const int sb  = (tid & 1) * 4;
#pragma unroll
    for (int j = 0; j < 4; j++) {
        const int seg = sb + j;
        cp16(sA + swz(row, seg), A + (size_t)(bm + row) * K_DIM + k0 + seg * 8);
        cp16(sB + swz(row, seg), B + (size_t)(bn + row) * K_DIM + k0 + seg * 8);
    }
    CP_COMMIT();
}

template <int MODE>
__device__ void gemm_hmma_body(const __half* __restrict__ A,
                               const __half* __restrict__ B,
                               const float* __restrict__ bias,
                               float* __restrict__ C,
                               __half* __restrict__ Ch,
                               float oscale) {
    extern __shared__ char sm[];
    const uint32_t smb = smem_u32(sm);

    const int tid  = threadIdx.x;
    const int wid  = tid >> 5;
    const int lane = tid & 31;
    const int wm   = wid >> 2;
    const int wn   = wid & 3;
    const int bm   = blockIdx.y * GBM;
    const int bn   = blockIdx.x * GBN;

    float acc[4][4][4];
#pragma unroll
    for (int i = 0; i < 4; i++)
#pragma unroll
        for (int j = 0; j < 4; j++)
#pragma unroll
            for (int r = 0; r < 4; r++) acc[i][j][r] = 0.f;

#pragma unroll
    for (int s = 0; s < NSTAGE; s++)
        load_chunk(A, B, bm, bn, s * GBK,
                   smb + s * STAGE_B, smb + s * STAGE_B + TILE_B);

    for (int c = 0; c < NCH; c++) {
        const int rem = NCH - 1 - c;
        if (rem >= 2)      CP_WAIT(2);
        else if (rem == 1) CP_WAIT(1);
        else               CP_WAIT(0);
        __syncthreads();

        const uint32_t aB = smb + (c % NSTAGE) * STAGE_B;
        const uint32_t bB = aB + TILE_B;

#pragma unroll
        for (int ks = 0; ks < 4; ks++) {
            uint32_t afr[4][4];
#pragma unroll
            for (int mi = 0; mi < 4; mi++) {
                const int row = wm * 64 + mi * 16 + (lane & 15);
                const int seg = ks * 2 + (lane >> 4);
                LDSM_X4(afr[mi], aB + swz(row, seg));
            }
            uint32_t bfr[2][4];
            const int g = lane >> 3;
#pragma unroll
            for (int np = 0; np < 2; np++) {
                const int row = wn * 32 + np * 16 + (g >> 1) * 8 + (lane & 7);
                const int seg = ks * 2 + (g & 1);
                LDSM_X4(bfr[np], bB + swz(row, seg));
            }
#pragma unroll
            for (int mi = 0; mi < 4; mi++) {
#pragma unroll
                for (int ni = 0; ni < 4; ni++)
                    mma16816h(acc[mi][ni], afr[mi], &bfr[ni >> 1][(ni & 1) * 2]);
            }
        }
        __syncthreads();

        if (c + NSTAGE < NCH)
            load_chunk(A, B, bm, bn, (c + NSTAGE) * GBK,
                       smb + (c % NSTAGE) * STAGE_B,
                       smb + (c % NSTAGE) * STAGE_B + TILE_B);
    }

#pragma unroll
    for (int mi = 0; mi < 4; mi++) {
#pragma unroll
        for (int ni = 0; ni < 4; ni++) {
            const int r0 = bm + wm * 64 + mi * 16 + (lane >> 2);
            const int c0 = bn + wn * 32 + ni * 8 + (lane & 3) * 2;
            if (MODE == 0) {
                float2 v0 = make_float2(acc[mi][ni][0], acc[mi][ni][1]);
                float2 v1 = make_float2(acc[mi][ni][2], acc[mi][ni][3]);
                if (bias) {
                    const float b0 = bias[c0], b1 = bias[c0 + 1];
                    v0.x += b0; v0.y += b1;
                    v1.x += b0; v1.y += b1;
                }
                *(float2*)&C[(size_t)r0 * N_DIM + c0]       = v0;
                *(float2*)&C[(size_t)(r0 + 8) * N_DIM + c0] = v1;
            } else {
                const int b  = r0 >> 10;
                const int t  = r0 & 1023;
                const int h  = c0 >> 6;
                const int dd = c0 & 63;
                const size_t base = (((size_t)(b * 16 + h) * 1024 + t) << 6) + dd;
                *(__half2*)&Ch[base] =
                    __floats2half2_rn(acc[mi][ni][0] * oscale, acc[mi][ni][1] * oscale);
                *(__half2*)&Ch[base + (8 << 6)] =
                    __floats2half2_rn(acc[mi][ni][2] * oscale, acc[mi][ni][3] * oscale);
            }
        }
    }
}

__global__ __launch_bounds__(256, 2) void qkv_hmma_kernel() {
    const int z = blockIdx.z;
    __half* dst = (z == 0) ? g_Qs2 : (z == 1) ? g_Ks2 : g_Vs;
    const float sc = (z == 0) ? QSCALE : 1.0f;
    gemm_hmma_body<1>(g_xs, g_Ws + (size_t)z * N_DIM * K_DIM, nullptr, nullptr, dst, sc);
}

__global__ __launch_bounds__(256, 2) void out_hmma_kernel(const float* __restrict__ bo,
                                                          float* __restrict__ out) {
    gemm_hmma_body<0>(g_As, g_Ws + (size_t)3 * N_DIM * K_DIM, bo, out, nullptr, 1.0f);
}

// ---------------------------------------------------------------------------
// conversions
// ---------------------------------------------------------------------------
__global__ void conv_x_kernel(const float* __restrict__ src) {
    const int i = blockIdx.x * blockDim.x + threadIdx.x;
    if (i >= M_ROWS * K_DIM / 4) return;
    float4 v = ((const float4*)src)[i];
    __half2* d = (__half2*)(g_xs) + i * 2;
    d[0] = __floats2half2_rn(v.x, v.y);
    d[1] = __floats2half2_rn(v.z, v.w);
}

__global__ void conv_w_kernel(const float* __restrict__ Wq, const float* __restrict__ Wk,
                              const float* __restrict__ Wv, const float* __restrict__ Wo) {
    const int z = blockIdx.z;
    const float* src = (z == 0) ? Wq : (z == 1) ? Wk : (z == 2) ? Wv : Wo;
    const int i = blockIdx.x * blockDim.x + threadIdx.x;
    if (i >= N_DIM * K_DIM / 4) return;
    float4 v = ((const float4*)src)[i];
    __half2* d = (__half2*)(g_Ws + (size_t)z * N_DIM * K_DIM) + i * 2;
    d[0] = __floats2half2_rn(v.x, v.y);
    d[1] = __floats2half2_rn(v.z, v.w);
}

// ---------------------------------------------------------------------------
// HMMA flash attention v3: 512 threads, q-tile 256, KV tile 64 keys,
// max-free softmax (Q pre-scaled by log2e/8; bare exp2; sum reduced once
// after the kt loop). 2-stage cp.async pipeline.
// ---------------------------------------------------------------------------
#define QLD 72
#define AQ_BYTES (256 * QLD * 2)              // 36864
#define AK_BYTES (64 * QLD * 2)               // 9216
#define KV_STAGE_B (2 * AK_BYTES)             // 18432
#define ATTN_SMEM (AQ_BYTES + 2 * KV_STAGE_B) // 73728

__device__ __forceinline__ void attn_load_q256(uint32_t sQ, int bh, int t0) {
    const int tid = threadIdx.x;
#pragma unroll
    for (int j = 0; j < 4; j++) {
        const int i = tid + j * 512;
        const int r = i >> 3, sg = i & 7;
        cp16(sQ + (r * QLD + sg * 8) * 2,
             g_Qs2 + (((size_t)bh * 1024 + t0 + r) << 6) + sg * 8);
    }
}
__device__ __forceinline__ void attn_load_kv64(uint32_t sKV, int bh, int t0) {
    const int tid = threadIdx.x;
    const int r = tid >> 3, sg = tid & 7;
    cp16(sKV + (r * QLD + sg * 8) * 2,
         g_Ks2 + (((size_t)bh * 1024 + t0 + r) << 6) + sg * 8);
    cp16(sKV + AK_BYTES + (r * QLD + sg * 8) * 2,
         g_Vs + (((size_t)bh * 1024 + t0 + r) << 6) + sg * 8);
    CP_COMMIT();
}

__global__ __launch_bounds__(512, 1) void attn_hmma_kernel()
{
    extern __shared__ char sm[];
    const uint32_t smb = smem_u32(sm);
    const uint32_t sQ   = smb;
    const uint32_t sKV0 = smb + AQ_BYTES;

    const int tid  = threadIdx.x;
    const int wid  = tid >> 5;
    const int lane = tid & 31;
    const int g    = lane >> 2;
    const int qt   = blockIdx.x;
    const int bh   = blockIdx.y;
    const int h    = bh & 15;
    const int cbase = h * DHEAD;
    const int qrow0 = (bh >> 4) * TSEQ + qt * 256;

    attn_load_q256(sQ, bh, qt * 256);
    attn_load_kv64(sKV0, bh, 0);
    attn_load_kv64(sKV0 + KV_STAGE_B, bh, 64);

    float acc_o[8][4];
#pragma unroll
    for (int i = 0; i < 8; i++)
#pragma unroll
        for (int r = 0; r < 4; r++) acc_o[i][r] = 0.f;
    float l0 = 0.f, l1 = 0.f;     // per-thread partial row sums

    for (int kt = 0; kt < 16; kt++) {
        if (kt < 15) CP_WAIT(1); else CP_WAIT(0);
        __syncthreads();

        const uint32_t sK = sKV0 + (kt & 1) * KV_STAGE_B;
        const uint32_t sV = sK + AK_BYTES;

        // ---- S = (Q*log2e/8) Kh^T ----
        float s_acc[8][4];
#pragma unroll
        for (int ni = 0; ni < 8; ni++)
#pragma unroll
            for (int r = 0; r < 4; r++) s_acc[ni][r] = 0.f;

        const int gg = lane >> 3;
#pragma unroll
        for (int ks = 0; ks < 4; ks++) {
            uint32_t a[4];
            LDSM_X4(a, sQ + ((wid * 16 + (lane & 15)) * QLD + ks * 16 + (lane >> 4) * 8) * 2);
            uint32_t bf[4][4];
#pragma unroll
            for (int np = 0; np < 4; np++) {
                const int row = np * 16 + (gg >> 1) * 8 + (lane & 7);
                LDSM_X4(bf[np], sK + (row * QLD + ks * 16 + (gg & 1) * 8) * 2);
            }
#pragma unroll
            for (int ni = 0; ni < 8; ni++)
                mma16816h(s_acc[ni], a, &bf[ni >> 1][(ni & 1) * 2]);
        }

        // ---- max-free softmax: P = exp2(S), accumulate row sums ----
#pragma unroll
        for (int ni = 0; ni < 8; ni++) {
            s_acc[ni][0] = exp2f(s_acc[ni][0]);
            s_acc[ni][1] = exp2f(s_acc[ni][1]);
            s_acc[ni][2] = exp2f(s_acc[ni][2]);
            s_acc[ni][3] = exp2f(s_acc[ni][3]);
            l0 += s_acc[ni][0] + s_acc[ni][1];
            l1 += s_acc[ni][2] + s_acc[ni][3];
        }

        // ---- O += P V : V via ldmatrix.trans ----
#pragma unroll
        for (int ks = 0; ks < 4; ks++) {
            uint32_t ph[4];
            {
                const float* t0 = s_acc[2 * ks];
                const float* t1 = s_acc[2 * ks + 1];
                ph[0] = packh2(t0[0], t0[1]);
                ph[1] = packh2(t0[2], t0[3]);
                ph[2] = packh2(t1[0], t1[1]);
                ph[3] = packh2(t1[2], t1[3]);
            }
            uint32_t vh[4][4];
#pragma unroll
            for (int np = 0; np < 4; np++) {
                const int row_t = ks * 16 + (gg & 1) * 8 + (lane & 7);
                const int col_d = np * 16 + (gg >> 1) * 8;
                LDSM_X4_T(vh[np], sV + (row_t * QLD + col_d) * 2);
            }
#pragma unroll
            for (int ni = 0; ni < 8; ni++)
                mma16816h(acc_o[ni], ph, &vh[ni >> 1][(ni & 1) * 2]);
        }

        __syncthreads();
        if (kt + 2 < 16)
            attn_load_kv64(sKV0 + (kt & 1) * KV_STAGE_B, bh, (kt + 2) * 64);
    }

    // ---- one-time row-sum reduction, normalize, write fp16 g_As ----
    l0 += __shfl_xor_sync(0xffffffffu, l0, 1);
    l0 += __shfl_xor_sync(0xffffffffu, l0, 2);
    l1 += __shfl_xor_sync(0xffffffffu, l1, 1);
    l1 += __shfl_xor_sync(0xffffffffu, l1, 2);
    const float inv0 = 1.0f / l0;
    const float inv1 = 1.0f / l1;
    const int row0 = qrow0 + wid * 16 + g;
#pragma unroll
    for (int ni = 0; ni < 8; ni++) {
        const int col = cbase + ni * 8 + (lane & 3) * 2;
        *(__half2*)(g_As + (size_t)row0 * K_DIM + col) =
            __floats2half2_rn(acc_o[ni][0] * inv0, acc_o[ni][1] * inv0);
        *(__half2*)(g_As + (size_t)(row0 + 8) * K_DIM + col) =
            __floats2half2_rn(acc_o[ni][2] * inv1, acc_o[ni][3] * inv1);
    }
}

// ---------------------------------------------------------------------------
// kernel_launch
// ---------------------------------------------------------------------------
extern "C" void kernel_launch(void* const* d_in, const int* in_sizes, int n_in,
                              void* d_out, int out_size)
{
    const float* x  = (const float*)d_in[0];
    const float* Wq = (const float*)d_in[1];
    const float* Wk = (const float*)d_in[2];
    const float* Wv = (const float*)d_in[3];
    const float* Wo = (const float*)d_in[4];
    const float* bo = (const float*)d_in[5];
    float* out = (float*)d_out;

    cudaFuncSetAttribute(qkv_hmma_kernel, cudaFuncAttributeMaxDynamicSharedMemorySize, GEMM_SMEM);
    cudaFuncSetAttribute(out_hmma_kernel, cudaFuncAttributeMaxDynamicSharedMemorySize, GEMM_SMEM);
    cudaFuncSetAttribute(attn_hmma_kernel, cudaFuncAttributeMaxDynamicSharedMemorySize, ATTN_SMEM);

    // 1) fp32 -> fp16 conversions
    {
        const int nx = M_ROWS * K_DIM / 4;
        conv_x_kernel<<<(nx + 255) / 256, 256>>>(x);
        const int nw = N_DIM * K_DIM / 4;
        conv_w_kernel<<<dim3((nw + 255) / 256, 1, 4), 256>>>(Wq, Wk, Wv, Wo);
    }

    // 2) QKV projections; Q pre-scaled by log2e/8 in epilogue
    qkv_hmma_kernel<<<dim3(N_DIM / GBN, M_ROWS / GBM, 3), 256, GEMM_SMEM>>>();

    // 3) attention (max-free softmax, 512 threads, 64-key tiles)
    attn_hmma_kernel<<<dim3(4, 64), 512, ATTN_SMEM>>>();

    // 4) output projection + bias
    out_hmma_kernel<<<dim3(N_DIM / GBN, M_ROWS / GBM), 256, GEMM_SMEM>>>(bo, out);
}

// round 16
// speedup vs baseline: 3.0552x; 1.0056x over previous
#include <cuda_runtime.h>
#include <cuda_bf16.h>
#include <cuda_fp16.h>
#include <math.h>
#include <stdint.h>
#include <string.h>

// ---------------------------------------------------------------------------
// Problem constants
// ---------------------------------------------------------------------------
#define M_ROWS 4096
#define K_DIM  1024
#define N_DIM  1024
#define HEADS  16
#define DHEAD  64
#define TSEQ   1024
#define BATCH  4

// Q pre-scale: 1/sqrt(64) * log2(e) so softmax exp becomes bare exp2
#define QSCALE 0.1803368801111137f

// fp16 scratch for projection GEMMs
__device__ __align__(16) __half g_xs[M_ROWS * K_DIM];
__device__ __align__(16) __half g_As[M_ROWS * K_DIM];
__device__ __align__(16) __half g_Ws[4 * N_DIM * K_DIM];

// attention fp16 operands, per-head [bh][t][64]
__device__ __align__(16) __half g_Qs2[64 * 1024 * 64];
__device__ __align__(16) __half g_Ks2[64 * 1024 * 64];
__device__ __align__(16) __half g_Vs[64 * 1024 * 64];

// ---------------------------------------------------------------------------
// PTX helpers
// ---------------------------------------------------------------------------
__device__ __forceinline__ uint32_t smem_u32(const void* p) {
    uint32_t a;
    asm("{ .reg .u64 t; cvta.to.shared.u64 t, %1; cvt.u32.u64 %0, t; }"
        : "=r"(a) : "l"(p));
    return a;
}
__device__ __forceinline__ void cp16(uint32_t s, const void* g) {
    asm volatile("cp.async.cg.shared.global [%0], [%1], 16;" :: "r"(s), "l"(g));
}
#define CP_COMMIT() asm volatile("cp.async.commit_group;" ::: "memory")
#define CP_WAIT(n)  asm volatile("cp.async.wait_group %0;" :: "n"(n) : "memory")

#define LDSM_X4(r, addr)                                                       \
    asm volatile("ldmatrix.sync.aligned.m8n8.x4.shared.b16 {%0,%1,%2,%3}, [%4];" \
                 : "=r"((r)[0]), "=r"((r)[1]), "=r"((r)[2]), "=r"((r)[3])      \
                 : "r"(addr))
#define LDSM_X4_T(r, addr)                                                     \
    asm volatile("ldmatrix.sync.aligned.m8n8.x4.trans.shared.b16 {%0,%1,%2,%3}, [%4];" \
                 : "=r"((r)[0]), "=r"((r)[1]), "=r"((r)[2]), "=r"((r)[3])      \
                 : "r"(addr))

__device__ __forceinline__ void mma16816h(float* c, const uint32_t* a,
                                          const uint32_t* b) {
    asm volatile(
        "mma.sync.aligned.m16n8k16.row.col.f32.f16.f16.f32 "
        "{%0,%1,%2,%3}, {%4,%5,%6,%7}, {%8,%9}, {%0,%1,%2,%3};"
        : "+f"(c[0]), "+f"(c[1]), "+f"(c[2]), "+f"(c[3])
        : "r"(a[0]), "r"(a[1]), "r"(a[2]), "r"(a[3]), "r"(b[0]), "r"(b[1]));
}

__device__ __forceinline__ uint32_t packh2(float x, float y) {
    __half2 t = __floats2half2_rn(x, y);
    uint32_t u;
    memcpy(&u, &t, 4);
    return u;
}

// ---------------------------------------------------------------------------
// HMMA fp16 NT GEMM (validated). MODE 0 = fp32 C (+bias); MODE 1 = per-head
// fp16 [bh][t][64], output scaled by `oscale`.
// ---------------------------------------------------------------------------
#define GBM 128
#define GBN 128
#define GBK 64
#define TILE_B  (128 * 128)
#define STAGE_B (2 * TILE_B)
#define NSTAGE  3
#define NCH     (K_DIM / GBK)            // 16
#define GEMM_SMEM (NSTAGE * STAGE_B)     // 98304

__device__ __forceinline__ uint32_t swz(uint32_t row, uint32_t seg) {
    return row * 128 + ((seg ^ (row & 7)) * 16);
}

__device__ __forceinline__ void load_chunk(const __half* __restrict__ A,
                                           const __half* __restrict__ B,
                                           int bm, int bn, int k0,
                                           uint32_t sA, uint32_t sB) {
    const int tid = threadIdx.x;
    const int row = tid >> 1;
    const int sb  = (tid & 1) * 4;
#pragma unroll
    for (int j = 0; j < 4; j++) {
        const int seg = sb + j;
        cp16(sA + swz(row, seg), A + (size_t)(bm + row) * K_DIM + k0 + seg * 8);
        cp16(sB + swz(row, seg), B + (size_t)(bn + row) * K_DIM + k0 + seg * 8);
    }
    CP_COMMIT();
}

template <int MODE>
__device__ void gemm_hmma_body(const __half* __restrict__ A,
                               const __half* __restrict__ B,
                               const float* __restrict__ bias,
                               float* __restrict__ C,
                               __half* __restrict__ Ch,
                               float oscale) {
    extern __shared__ char sm[];
    const uint32_t smb = smem_u32(sm);

    const int tid  = threadIdx.x;
    const int wid  = tid >> 5;
    const int lane = tid & 31;
    const int wm   = wid >> 2;
    const int wn   = wid & 3;
    const int bm   = blockIdx.y * GBM;
    const int bn   = blockIdx.x * GBN;

    float acc[4][4][4];
#pragma unroll
    for (int i = 0; i < 4; i++)
#pragma unroll
        for (int j = 0; j < 4; j++)
#pragma unroll
            for (int r = 0; r < 4; r++) acc[i][j][r] = 0.f;

#pragma unroll
    for (int s = 0; s < NSTAGE; s++)
        load_chunk(A, B, bm, bn, s * GBK,
                   smb + s * STAGE_B, smb + s * STAGE_B + TILE_B);

    for (int c = 0; c < NCH; c++) {
        const int rem = NCH - 1 - c;
        if (rem >= 2)      CP_WAIT(2);
        else if (rem == 1) CP_WAIT(1);
        else               CP_WAIT(0);
        __syncthreads();

        const uint32_t aB = smb + (c % NSTAGE) * STAGE_B;
        const uint32_t bB = aB + TILE_B;

#pragma unroll
        for (int ks = 0; ks < 4; ks++) {
            uint32_t afr[4][4];
#pragma unroll
            for (int mi = 0; mi < 4; mi++) {
                const int row = wm * 64 + mi * 16 + (lane & 15);
                const int seg = ks * 2 + (lane >> 4);
                LDSM_X4(afr[mi], aB + swz(row, seg));
            }
            uint32_t bfr[2][4];
            const int g = lane >> 3;
#pragma unroll
            for (int np = 0; np < 2; np++) {
                const int row = wn * 32 + np * 16 + (g >> 1) * 8 + (lane & 7);
                const int seg = ks * 2 + (g & 1);
                LDSM_X4(bfr[np], bB + swz(row, seg));
            }
#pragma unroll
            for (int mi = 0; mi < 4; mi++) {
#pragma unroll
                for (int ni = 0; ni < 4; ni++)
                    mma16816h(acc[mi][ni], afr[mi], &bfr[ni >> 1][(ni & 1) * 2]);
            }
        }
        __syncthreads();

        if (c + NSTAGE < NCH)
            load_chunk(A, B, bm, bn, (c + NSTAGE) * GBK,
                       smb + (c % NSTAGE) * STAGE_B,
                       smb + (c % NSTAGE) * STAGE_B + TILE_B);
    }

#pragma unroll
    for (int mi = 0; mi < 4; mi++) {
#pragma unroll
        for (int ni = 0; ni < 4; ni++) {
            const int r0 = bm + wm * 64 + mi * 16 + (lane >> 2);
            const int c0 = bn + wn * 32 + ni * 8 + (lane & 3) * 2;
            if (MODE == 0) {
                float2 v0 = make_float2(acc[mi][ni][0], acc[mi][ni][1]);
                float2 v1 = make_float2(acc[mi][ni][2], acc[mi][ni][3]);
                if (bias) {
                    const float b0 = bias[c0], b1 = bias[c0 + 1];
                    v0.x += b0; v0.y += b1;
                    v1.x += b0; v1.y += b1;
                }
                *(float2*)&C[(size_t)r0 * N_DIM + c0]       = v0;
                *(float2*)&C[(size_t)(r0 + 8) * N_DIM + c0] = v1;
            } else {
                const int b  = r0 >> 10;
                const int t  = r0 & 1023;
                const int h  = c0 >> 6;
                const int dd = c0 & 63;
                const size_t base = (((size_t)(b * 16 + h) * 1024 + t) << 6) + dd;
                *(__half2*)&Ch[base] =
                    __floats2half2_rn(acc[mi][ni][0] * oscale, acc[mi][ni][1] * oscale);
                *(__half2*)&Ch[base + (8 << 6)] =
                    __floats2half2_rn(acc[mi][ni][2] * oscale, acc[mi][ni][3] * oscale);
            }
        }
    }
}

__global__ __launch_bounds__(256, 2) void qkv_hmma_kernel() {
    const int z = blockIdx.z;
    __half* dst = (z == 0) ? g_Qs2 : (z == 1) ? g_Ks2 : g_Vs;
    const float sc = (z == 0) ? QSCALE : 1.0f;
    gemm_hmma_body<1>(g_xs, g_Ws + (size_t)z * N_DIM * K_DIM, nullptr, nullptr, dst, sc);
}

__global__ __launch_bounds__(256, 2) void out_hmma_kernel(const float* __restrict__ bo,
                                                          float* __restrict__ out) {
    gemm_hmma_body<0>(g_As, g_Ws + (size_t)3 * N_DIM * K_DIM, bo, out, nullptr, 1.0f);
}

// ---------------------------------------------------------------------------
// conversions
// ---------------------------------------------------------------------------
__global__ void conv_x_kernel(const float* __restrict__ src) {
    const int i = blockIdx.x * blockDim.x + threadIdx.x;
    if (i >= M_ROWS * K_DIM / 4) return;
    float4 v = ((const float4*)src)[i];
    __half2* d = (__half2*)(g_xs) + i * 2;
    d[0] = __floats2half2_rn(v.x, v.y);
    d[1] = __floats2half2_rn(v.z, v.w);
}

__global__ void conv_w_kernel(const float* __restrict__ Wq, const float* __restrict__ Wk,
                              const float* __restrict__ Wv, const float* __restrict__ Wo) {
    const int z = blockIdx.z;
    const float* src = (z == 0) ? Wq : (z == 1) ? Wk : (z == 2) ? Wv : Wo;
    const int i = blockIdx.x * blockDim.x + threadIdx.x;
    if (i >= N_DIM * K_DIM / 4) return;
    float4 v = ((const float4*)src)[i];
    __half2* d = (__half2*)(g_Ws + (size_t)z * N_DIM * K_DIM) + i * 2;
    d[0] = __floats2half2_rn(v.x, v.y);
    d[1] = __floats2half2_rn(v.z, v.w);
}

// ---------------------------------------------------------------------------
// HMMA flash attention v4: 256 threads (8 warps), q-tile 128, KV tile 64,
// 16 kt iterations, max-free softmax, 2-stage cp.async pipeline.
// Smem 54 KB -> 2 CTAs/SM; independent CTA barrier phases overlay
// one CTA's exp2 phase with the other's MMA burst.
// ---------------------------------------------------------------------------
#define QLD 72
#define AQ_BYTES (128 * QLD * 2)              // 18432
#define AK_BYTES (64 * QLD * 2)               // 9216
#define KV_STAGE_B (2 * AK_BYTES)             // 18432
#define ATTN_SMEM (AQ_BYTES + 2 * KV_STAGE_B) // 55296

__device__ __forceinline__ void attn_load_q128(uint32_t sQ, int bh, int t0) {
    const int tid = threadIdx.x;
#pragma unroll
    for (int j = 0; j < 4; j++) {
        const int i = tid + j * 256;          // 0..1023
        const int r = i >> 3, sg = i & 7;
        cp16(sQ + (r * QLD + sg * 8) * 2,
             g_Qs2 + (((size_t)bh * 1024 + t0 + r) << 6) + sg * 8);
    }
}
__device__ __forceinline__ void attn_load_kv64(uint32_t sKV, int bh, int t0) {
    const int tid = threadIdx.x;
#pragma unroll
    for (int j = 0; j < 2; j++) {
        const int i = tid + j * 256;          // 0..511
        const int r = i >> 3, sg = i & 7;
        cp16(sKV + (r * QLD + sg * 8) * 2,
             g_Ks2 + (((size_t)bh * 1024 + t0 + r) << 6) + sg * 8);
        cp16(sKV + AK_BYTES + (r * QLD + sg * 8) * 2,
             g_Vs + (((size_t)bh * 1024 + t0 + r) << 6) + sg * 8);
    }
    CP_COMMIT();
}

__global__ __launch_bounds__(256, 2) void attn_hmma_kernel()
{
    extern __shared__ char sm[];
    const uint32_t smb = smem_u32(sm);
    const uint32_t sQ   = smb;
    const uint32_t sKV0 = smb + AQ_BYTES;

    const int tid  = threadIdx.x;
    const int wid  = tid >> 5;                // 0..7
    const int lane = tid & 31;
    const int g    = lane >> 2;
    const int qt   = blockIdx.x;              // 0..7
    const int bh   = blockIdx.y;
    const int h    = bh & 15;
    const int cbase = h * DHEAD;
    const int qrow0 = (bh >> 4) * TSEQ + qt * 128;

    attn_load_q128(sQ, bh, qt * 128);
    attn_load_kv64(sKV0, bh, 0);
    attn_load_kv64(sKV0 + KV_STAGE_B, bh, 64);

    float acc_o[8][4];
#pragma unroll
    for (int i = 0; i < 8; i++)
#pragma unroll
        for (int r = 0; r < 4; r++) acc_o[i][r] = 0.f;
    float l0 = 0.f, l1 = 0.f;

    for (int kt = 0; kt < 16; kt++) {
        if (kt < 15) CP_WAIT(1); else CP_WAIT(0);
        __syncthreads();

        const uint32_t sK = sKV0 + (kt & 1) * KV_STAGE_B;
        const uint32_t sV = sK + AK_BYTES;

        // ---- S = (Q*log2e/8) Kh^T ----
        float s_acc[8][4];
#pragma unroll
        for (int ni = 0; ni < 8; ni++)
#pragma unroll
            for (int r = 0; r < 4; r++) s_acc[ni][r] = 0.f;

        const int gg = lane >> 3;
#pragma unroll
        for (int ks = 0; ks < 4; ks++) {
            uint32_t a[4];
            LDSM_X4(a, sQ + ((wid * 16 + (lane & 15)) * QLD + ks * 16 + (lane >> 4) * 8) * 2);
            uint32_t bf[4][4];
#pragma unroll
            for (int np = 0; np < 4; np++) {
                const int row = np * 16 + (gg >> 1) * 8 + (lane & 7);
                LDSM_X4(bf[np], sK + (row * QLD + ks * 16 + (gg & 1) * 8) * 2);
            }
#pragma unroll
            for (int ni = 0; ni < 8; ni++)
                mma16816h(s_acc[ni], a, &bf[ni >> 1][(ni & 1) * 2]);
        }

        // ---- max-free softmax: P = exp2(S), accumulate row sums ----
#pragma unroll
        for (int ni = 0; ni < 8; ni++) {
            s_acc[ni][0] = exp2f(s_acc[ni][0]);
            s_acc[ni][1] = exp2f(s_acc[ni][1]);
            s_acc[ni][2] = exp2f(s_acc[ni][2]);
            s_acc[ni][3] = exp2f(s_acc[ni][3]);
            l0 += s_acc[ni][0] + s_acc[ni][1];
            l1 += s_acc[ni][2] + s_acc[ni][3];
        }

        // ---- O += P V : V via ldmatrix.trans ----
#pragma unroll
        for (int ks = 0; ks < 4; ks++) {
            uint32_t ph[4];
            {
                const float* t0 = s_acc[2 * ks];
                const float* t1 = s_acc[2 * ks + 1];
                ph[0] = packh2(t0[0], t0[1]);
                ph[1] = packh2(t0[2], t0[3]);
                ph[2] = packh2(t1[0], t1[1]);
                ph[3] = packh2(t1[2], t1[3]);
            }
            uint32_t vh[4][4];
#pragma unroll
            for (int np = 0; np < 4; np++) {
                const int row_t = ks * 16 + (gg & 1) * 8 + (lane & 7);
                const int col_d = np * 16 + (gg >> 1) * 8;
                LDSM_X4_T(vh[np], sV + (row_t * QLD + col_d) * 2);
            }
#pragma unroll
            for (int ni = 0; ni < 8; ni++)
                mma16816h(acc_o[ni], ph, &vh[ni >> 1][(ni & 1) * 2]);
        }

        __syncthreads();
        if (kt + 2 < 16)
            attn_load_kv64(sKV0 + (kt & 1) * KV_STAGE_B, bh, (kt + 2) * 64);
    }

    // ---- one-time row-sum reduction, normalize, write fp16 g_As ----
    l0 += __shfl_xor_sync(0xffffffffu, l0, 1);
    l0 += __shfl_xor_sync(0xffffffffu, l0, 2);
    l1 += __shfl_xor_sync(0xffffffffu, l1, 1);
    l1 += __shfl_xor_sync(0xffffffffu, l1, 2);
    const float inv0 = 1.0f / l0;
    const float inv1 = 1.0f / l1;
    const int row0 = qrow0 + wid * 16 + g;
#pragma unroll
    for (int ni = 0; ni < 8; ni++) {
        const int col = cbase + ni * 8 + (lane & 3) * 2;
        *(__half2*)(g_As + (size_t)row0 * K_DIM + col) =
            __floats2half2_rn(acc_o[ni][0] * inv0, acc_o[ni][1] * inv0);
        *(__half2*)(g_As + (size_t)(row0 + 8) * K_DIM + col) =
            __floats2half2_rn(acc_o[ni][2] * inv1, acc_o[ni][3] * inv1);
    }
}

// ---------------------------------------------------------------------------
// kernel_launch
// ---------------------------------------------------------------------------
extern "C" void kernel_launch(void* const* d_in, const int* in_sizes, int n_in,
                              void* d_out, int out_size)
{
    const float* x  = (const float*)d_in[0];
    const float* Wq = (const float*)d_in[1];
    const float* Wk = (const float*)d_in[2];
    const float* Wv = (const float*)d_in[3];
    const float* Wo = (const float*)d_in[4];
    const float* bo = (const float*)d_in[5];
    float* out = (float*)d_out;

    cudaFuncSetAttribute(qkv_hmma_kernel, cudaFuncAttributeMaxDynamicSharedMemorySize, GEMM_SMEM);
    cudaFuncSetAttribute(out_hmma_kernel, cudaFuncAttributeMaxDynamicSharedMemorySize, GEMM_SMEM);
    cudaFuncSetAttribute(attn_hmma_kernel, cudaFuncAttributeMaxDynamicSharedMemorySize, ATTN_SMEM);

    // 1) fp32 -> fp16 conversions
    {
        const int nx = M_ROWS * K_DIM / 4;
        conv_x_kernel<<<(nx + 255) / 256, 256>>>(x);
        const int nw = N_DIM * K_DIM / 4;
        conv_w_kernel<<<dim3((nw + 255) / 256, 1, 4), 256>>>(Wq, Wk, Wv, Wo);
    }

    // 2) QKV projections; Q pre-scaled by log2e/8 in epilogue
    qkv_hmma_kernel<<<dim3(N_DIM / GBN, M_ROWS / GBM, 3), 256, GEMM_SMEM>>>();

    // 3) attention (max-free softmax, 256 threads, 2 CTAs/SM dephased)
    attn_hmma_kernel<<<dim3(8, 64), 256, ATTN_SMEM>>>();

    // 4) output projection + bias
    out_hmma_kernel<<<dim3(N_DIM / GBN, M_ROWS / GBM), 256, GEMM_SMEM>>>(bo, out);
}

// round 17
// speedup vs baseline: 3.0629x; 1.0025x over previous
#include <cuda_runtime.h>
#include <cuda_bf16.h>
#include <cuda_fp16.h>
#include <math.h>
#include <stdint.h>
#include <string.h>

// ---------------------------------------------------------------------------
// Problem constants
// ---------------------------------------------------------------------------
#define M_ROWS 4096
#define K_DIM  1024
#define N_DIM  1024
#define HEADS  16
#define DHEAD  64
#define TSEQ   1024
#define BATCH  4

// Q pre-scale: 1/sqrt(64) * log2(e) so softmax exp becomes bare exp2
#define QSCALE 0.1803368801111137f
// softmax shift (log2 domain), cancels in P/l; keeps packed fp16 S accurate
#define SSHIFT 8.0f

// fp16 scratch for projection GEMMs
__device__ __align__(16) __half g_xs[M_ROWS * K_DIM];
__device__ __align__(16) __half g_As[M_ROWS * K_DIM];
__device__ __align__(16) __half g_Ws[4 * N_DIM * K_DIM];

// attention fp16 operands, per-head [bh][t][64]
__device__ __align__(16) __half g_Qs2[64 * 1024 * 64];
__device__ __align__(16) __half g_Ks2[64 * 1024 * 64];
__device__ __align__(16) __half g_Vs[64 * 1024 * 64];

// ---------------------------------------------------------------------------
// PTX helpers
// ---------------------------------------------------------------------------
__device__ __forceinline__ uint32_t smem_u32(const void* p) {
    uint32_t a;
    asm("{ .reg .u64 t; cvta.to.shared.u64 t, %1; cvt.u32.u64 %0, t; }"
        : "=r"(a) : "l"(p));
    return a;
}
__device__ __forceinline__ void cp16(uint32_t s, const void* g) {
    asm volatile("cp.async.cg.shared.global [%0], [%1], 16;" :: "r"(s), "l"(g));
}
#define CP_COMMIT() asm volatile("cp.async.commit_group;" ::: "memory")
#define CP_WAIT(n)  asm volatile("cp.async.wait_group %0;" :: "n"(n) : "memory")

#define LDSM_X4(r, addr)                                                       \
    asm volatile("ldmatrix.sync.aligned.m8n8.x4.shared.b16 {%0,%1,%2,%3}, [%4];" \
                 : "=r"((r)[0]), "=r"((r)[1]), "=r"((r)[2]), "=r"((r)[3])      \
                 : "r"(addr))
#define LDSM_X4_T(r, addr)                                                     \
    asm volatile("ldmatrix.sync.aligned.m8n8.x4.trans.shared.b16 {%0,%1,%2,%3}, [%4];" \
                 : "=r"((r)[0]), "=r"((r)[1]), "=r"((r)[2]), "=r"((r)[3])      \
                 : "r"(addr))
#define EX2_F16X2(r) asm volatile("ex2.approx.f16x2 %0, %0;" : "+r"(r))

__device__ __forceinline__ void mma16816h(float* c, const uint32_t* a,
                                          const uint32_t* b) {
    asm volatile(
        "mma.sync.aligned.m16n8k16.row.col.f32.f16.f16.f32 "
        "{%0,%1,%2,%3}, {%4,%5,%6,%7}, {%8,%9}, {%0,%1,%2,%3};"
        : "+f"(c[0]), "+f"(c[1]), "+f"(c[2]), "+f"(c[3])
        : "r"(a[0]), "r"(a[1]), "r"(a[2]), "r"(a[3]), "r"(b[0]), "r"(b[1]));
}

__device__ __forceinline__ uint32_t packh2(float x, float y) {
    __half2 t = __floats2half2_rn(x, y);
    uint32_t u;
    memcpy(&u, &t, 4);
    return u;
}

// ---------------------------------------------------------------------------
// HMMA fp16 NT GEMM (validated). MODE 0 = fp32 C (+bias); MODE 1 = per-head
// fp16 [bh][t][64], output scaled by `oscale`.
// ---------------------------------------------------------------------------
#define GBM 128
#define GBN 128
#define GBK 64
#define TILE_B  (128 * 128)
#define STAGE_B (2 * TILE_B)
#define NSTAGE  3
#define NCH     (K_DIM / GBK)            // 16
#define GEMM_SMEM (NSTAGE * STAGE_B)     // 98304

__device__ __forceinline__ uint32_t swz(uint32_t row, uint32_t seg) {
    return row * 128 + ((seg ^ (row & 7)) * 16);
}

__device__ __forceinline__ void load_chunk(const __half* __restrict__ A,
                                           const __half* __restrict__ B,
                                           int bm, int bn, int k0,
                                           uint32_t sA, uint32_t sB) {
    const int tid = threadIdx.x;
    const int row = tid >> 1;
    const int sb  = (tid & 1) * 4;
#pragma unroll
    for (int j = 0; j < 4; j++) {
        const int seg = sb + j;
        cp16(sA + swz(row, seg), A + (size_t)(bm + row) * K_DIM + k0 + seg * 8);
        cp16(sB + swz(row, seg), B + (size_t)(bn + row) * K_DIM + k0 + seg * 8);
    }
    CP_COMMIT();
}

template <int MODE>
__device__ void gemm_hmma_body(const __half* __restrict__ A,
                               const __half* __restrict__ B,
                               const float* __restrict__ bias,
                               float* __restrict__ C,
                               __half* __restrict__ Ch,
                               float oscale) {
    extern __shared__ char sm[];
    const uint32_t smb = smem_u32(sm);

    const int tid  = threadIdx.x;
    const int wid  = tid >> 5;
    const int lane = tid & 31;
    const int wm   = wid >> 2;
    const int wn   = wid & 3;
    const int bm   = blockIdx.y * GBM;
    const int bn   = blockIdx.x * GBN;

    float acc[4][4][4];
#pragma unroll
    for (int i = 0; i < 4; i++)
#pragma unroll
        for (int j = 0; j < 4; j++)
#pragma unroll
            for (int r = 0; r < 4; r++) acc[i][j][r] = 0.f;

#pragma unroll
    for (int s = 0; s < NSTAGE; s++)
        load_chunk(A, B, bm, bn, s * GBK,
                   smb + s * STAGE_B, smb + s * STAGE_B + TILE_B);

    for (int c = 0; c < NCH; c++) {
        const int rem = NCH - 1 - c;
        if (rem >= 2)      CP_WAIT(2);
        else if (rem == 1) CP_WAIT(1);
        else               CP_WAIT(0);
        __syncthreads();

        const uint32_t aB = smb + (c % NSTAGE) * STAGE_B;
        const uint32_t bB = aB + TILE_B;

#pragma unroll
        for (int ks = 0; ks < 4; ks++) {
            uint32_t afr[4][4];
#pragma unroll
            for (int mi = 0; mi < 4; mi++) {
                const int row = wm * 64 + mi * 16 + (lane & 15);
                const int seg = ks * 2 + (lane >> 4);
                LDSM_X4(afr[mi], aB + swz(row, seg));
            }
            uint32_t bfr[2][4];
            const int g = lane >> 3;
#pragma unroll
            for (int np = 0; np < 2; np++) {
                const int row = wn * 32 + np * 16 + (g >> 1) * 8 + (lane & 7);
                const int seg = ks * 2 + (g & 1);
                LDSM_X4(bfr[np], bB + swz(row, seg));
            }
#pragma unroll
            for (int mi = 0; mi < 4; mi++) {
#pragma unroll
                for (int ni = 0; ni < 4; ni++)
                    mma16816h(acc[mi][ni], afr[mi], &bfr[ni >> 1][(ni & 1) * 2]);
            }
        }
        __syncthreads();

        if (c + NSTAGE < NCH)
            load_chunk(A, B, bm, bn, (c + NSTAGE) * GBK,
                       smb + (c % NSTAGE) * STAGE_B,
                       smb + (c % NSTAGE) * STAGE_B + TILE_B);
    }

#pragma unroll
    for (int mi = 0; mi < 4; mi++) {
#pragma unroll
        for (int ni = 0; ni < 4; ni++) {
            const int r0 = bm + wm * 64 + mi * 16 + (lane >> 2);
            const int c0 = bn + wn * 32 + ni * 8 + (lane & 3) * 2;
            if (MODE == 0) {
                float2 v0 = make_float2(acc[mi][ni][0], acc[mi][ni][1]);
                float2 v1 = make_float2(acc[mi][ni][2], acc[mi][ni][3]);
                if (bias) {
                    const float b0 = bias[c0], b1 = bias[c0 + 1];
                    v0.x += b0; v0.y += b1;
                    v1.x += b0; v1.y += b1;
                }
                *(float2*)&C[(size_t)r0 * N_DIM + c0]       = v0;
                *(float2*)&C[(size_t)(r0 + 8) * N_DIM + c0] = v1;
            } else {
                const int b  = r0 >> 10;
                const int t  = r0 & 1023;
                const int h  = c0 >> 6;
                const int dd = c0 & 63;
                const size_t base = (((size_t)(b * 16 + h) * 1024 + t) << 6) + dd;
                *(__half2*)&Ch[base] =
                    __floats2half2_rn(acc[mi][ni][0] * oscale, acc[mi][ni][1] * oscale);
                *(__half2*)&Ch[base + (8 << 6)] =
                    __floats2half2_rn(acc[mi][ni][2] * oscale, acc[mi][ni][3] * oscale);
            }
        }
    }
}

__global__ __launch_bounds__(256, 2) void qkv_hmma_kernel() {
    const int z = blockIdx.z;
    __half* dst = (z == 0) ? g_Qs2 : (z == 1) ? g_Ks2 : g_Vs;
    const float sc = (z == 0) ? QSCALE : 1.0f;
    gemm_hmma_body<1>(g_xs, g_Ws + (size_t)z * N_DIM * K_DIM, nullptr, nullptr, dst, sc);
}

__global__ __launch_bounds__(256, 2) void out_hmma_kernel(const float* __restrict__ bo,
                                                          float* __restrict__ out) {
    gemm_hmma_body<0>(g_As, g_Ws + (size_t)3 * N_DIM * K_DIM, bo, out, nullptr, 1.0f);
}

// ---------------------------------------------------------------------------
// conversions
// ---------------------------------------------------------------------------
__global__ void conv_x_kernel(const float* __restrict__ src) {
    const int i = blockIdx.x * blockDim.x + threadIdx.x;
    if (i >= M_ROWS * K_DIM / 4) return;
    float4 v = ((const float4*)src)[i];
    __half2* d = (__half2*)(g_xs) + i * 2;
    d[0] = __floats2half2_rn(v.x, v.y);
    d[1] = __floats2half2_rn(v.z, v.w);
}

__global__ void conv_w_kernel(const float* __restrict__ Wq, const float* __restrict__ Wk,
                              const float* __restrict__ Wv, const float* __restrict__ Wo) {
    const int z = blockIdx.z;
    const float* src = (z == 0) ? Wq : (z == 1) ? Wk : (z == 2) ? Wv : Wo;
    const int i = blockIdx.x * blockDim.x + threadIdx.x;
    if (i >= N_DIM * K_DIM / 4) return;
    float4 v = ((const float4*)src)[i];
    __half2* d = (__half2*)(g_Ws + (size_t)z * N_DIM * K_DIM) + i * 2;
    d[0] = __floats2half2_rn(v.x, v.y);
    d[1] = __floats2half2_rn(v.z, v.w);
}

// ---------------------------------------------------------------------------
// HMMA flash attention v5: 256 threads, q-tile 128, KV tile 64, 2 CTAs/SM.
// Max-free softmax with:
//   - accumulator-initialized shift (s_acc starts at -SSHIFT; cancels in P/l)
//   - ex2.approx.f16x2 on packed S (half the MUFU ops, P born as A-fragments)
//   - row sums via ones-column MMA (V smem col 64 = 1.0, written once/buffer)
// ---------------------------------------------------------------------------
#define QLD 72
#define AQ_BYTES (128 * QLD * 2)              // 18432
#define AK_BYTES (64 * QLD * 2)               // 9216
#define KV_STAGE_B (2 * AK_BYTES)             // 18432
#define ATTN_SMEM (AQ_BYTES + 2 * KV_STAGE_B + 64)  // +pad for LDSM_T overshoot

__device__ __forceinline__ void attn_load_q128(uint32_t sQ, int bh, int t0) {
    const int tid = threadIdx.x;
#pragma unroll
    for (int j = 0; j < 4; j++) {
        const int i = tid + j * 256;
        const int r = i >> 3, sg = i & 7;
        cp16(sQ + (r * QLD + sg * 8) * 2,
             g_Qs2 + (((size_t)bh * 1024 + t0 + r) << 6) + sg * 8);
    }
}
__device__ __forceinline__ void attn_load_kv64(uint32_t sKV, int bh, int t0) {
    const int tid = threadIdx.x;
#pragma unroll
    for (int j = 0; j < 2; j++) {
        const int i = tid + j * 256;
        const int r = i >> 3, sg = i & 7;
        cp16(sKV + (r * QLD + sg * 8) * 2,
             g_Ks2 + (((size_t)bh * 1024 + t0 + r) << 6) + sg * 8);
        cp16(sKV + AK_BYTES + (r * QLD + sg * 8) * 2,
             g_Vs + (((size_t)bh * 1024 + t0 + r) << 6) + sg * 8);
    }
    CP_COMMIT();
}

__global__ __launch_bounds__(256, 2) void attn_hmma_kernel()
{
    extern __shared__ char sm[];
    const uint32_t smb = smem_u32(sm);
    const uint32_t sQ   = smb;
    const uint32_t sKV0 = smb + AQ_BYTES;

    const int tid  = threadIdx.x;
    const int wid  = tid >> 5;
    const int lane = tid & 31;
    const int g    = lane >> 2;
    const int qt   = blockIdx.x;
    const int bh   = blockIdx.y;
    const int h    = bh & 15;
    const int cbase = h * DHEAD;
    const int qrow0 = (bh >> 4) * TSEQ + qt * 128;

    attn_load_q128(sQ, bh, qt * 128);
    attn_load_kv64(sKV0, bh, 0);
    attn_load_kv64(sKV0 + KV_STAGE_B, bh, 64);

    // one-time: ones in V smem col 64 of BOTH ring buffers (cp.async never
    // writes cols 64-71, so these persist across reloads). zeros in 65-71.
    if (tid < 64) {
        __half* v0 = (__half*)(sm + AQ_BYTES + AK_BYTES) + tid * QLD + 64;
        __half* v1 = (__half*)(sm + AQ_BYTES + KV_STAGE_B + AK_BYTES) + tid * QLD + 64;
        v0[0] = __float2half(1.0f);
        v1[0] = __float2half(1.0f);
#pragma unroll
        for (int c = 1; c < 8; c++) { v0[c] = __half(0); v1[c] = __half(0); }
    }

    float acc_o[8][4];
#pragma unroll
    for (int i = 0; i < 8; i++)
#pragma unroll
        for (int r = 0; r < 4; r++) acc_o[i][r] = 0.f;
    float acc_l[4] = {0.f, 0.f, 0.f, 0.f};

    for (int kt = 0; kt < 16; kt++) {
        if (kt < 15) CP_WAIT(1); else CP_WAIT(0);
        __syncthreads();

        const uint32_t sK = sKV0 + (kt & 1) * KV_STAGE_B;
        const uint32_t sV = sK + AK_BYTES;

        // ---- S = (Q*log2e/8) Kh^T - SSHIFT (via accumulator init) ----
        float s_acc[8][4];
#pragma unroll
        for (int ni = 0; ni < 8; ni++)
#pragma unroll
            for (int r = 0; r < 4; r++) s_acc[ni][r] = -SSHIFT;

        const int gg = lane >> 3;
#pragma unroll
        for (int ks = 0; ks < 4; ks++) {
            uint32_t a[4];
            LDSM_X4(a, sQ + ((wid * 16 + (lane & 15)) * QLD + ks * 16 + (lane >> 4) * 8) * 2);
            uint32_t bf[4][4];
#pragma unroll
            for (int np = 0; np < 4; np++) {
                const int row = np * 16 + (gg >> 1) * 8 + (lane & 7);
                LDSM_X4(bf[np], sK + (row * QLD + ks * 16 + (gg & 1) * 8) * 2);
            }
#pragma unroll
            for (int ni = 0; ni < 8; ni++)
                mma16816h(s_acc[ni], a, &bf[ni >> 1][(ni & 1) * 2]);
        }

        // ---- pack S to fp16 pairs, exp2 in f16x2 (P born as A-fragments) --
        uint32_t pfr[4][4];
#pragma unroll
        for (int ks = 0; ks < 4; ks++) {
            const float* t0 = s_acc[2 * ks];
            const float* t1 = s_acc[2 * ks + 1];
            pfr[ks][0] = packh2(t0[0], t0[1]);
            pfr[ks][1] = packh2(t0[2], t0[3]);
            pfr[ks][2] = packh2(t1[0], t1[1]);
            pfr[ks][3] = packh2(t1[2], t1[3]);
            EX2_F16X2(pfr[ks][0]);
            EX2_F16X2(pfr[ks][1]);
            EX2_F16X2(pfr[ks][2]);
            EX2_F16X2(pfr[ks][3]);
        }

        // ---- O += P V (V via ldmatrix.trans); l += P * ones(col 64) ----
#pragma unroll
        for (int ks = 0; ks < 4; ks++) {
            uint32_t vh[4][4], vl1[4];
#pragma unroll
            for (int np = 0; np < 4; np++) {
                const int row_t = ks * 16 + (gg & 1) * 8 + (lane & 7);
                const int col_d = np * 16 + (gg >> 1) * 8;
                LDSM_X4_T(vh[np], sV + (row_t * QLD + col_d) * 2);
            }
            {
                const int row_t = ks * 16 + (gg & 1) * 8 + (lane & 7);
                const int col_d = 64 + (gg >> 1) * 8;   // gg>=2 lanes read pad
                LDSM_X4_T(vl1, sV + (row_t * QLD + col_d) * 2);
            }
#pragma unroll
            for (int ni = 0; ni < 8; ni++)
                mma16816h(acc_o[ni], pfr[ks], &vh[ni >> 1][(ni & 1) * 2]);
            mma16816h(acc_l, pfr[ks], &vl1[0]);
        }

        __syncthreads();
        if (kt + 2 < 16)
            attn_load_kv64(sKV0 + (kt & 1) * KV_STAGE_B, bh, (kt + 2) * 64);
    }

    // ---- l lives in quad-leader's acc_l[0]/acc_l[2]; broadcast, write ----
    const float l0 = __shfl_sync(0xffffffffu, acc_l[0], lane & 28);
    const float l1 = __shfl_sync(0xffffffffu, acc_l[2], lane & 28);
    const float inv0 = 1.0f / l0;
    const float inv1 = 1.0f / l1;
    const int row0 = qrow0 + wid * 16 + g;
#pragma unroll
    for (int ni = 0; ni < 8; ni++) {
        const int col = cbase + ni * 8 + (lane & 3) * 2;
        *(__half2*)(g_As + (size_t)row0 * K_DIM + col) =
            __floats2half2_rn(acc_o[ni][0] * inv0, acc_o[ni][1] * inv0);
        *(__half2*)(g_As + (size_t)(row0 + 8) * K_DIM + col) =
            __floats2half2_rn(acc_o[ni][2] * inv1, acc_o[ni][3] * inv1);
    }
}

// ---------------------------------------------------------------------------
// kernel_launch
// ---------------------------------------------------------------------------
extern "C" void kernel_launch(void* const* d_in, const int* in_sizes, int n_in,
                              void* d_out, int out_size)
{
    const float* x  = (const float*)d_in[0];
    const float* Wq = (const float*)d_in[1];
    const float* Wk = (const float*)d_in[2];
    const float* Wv = (const float*)d_in[3];
    const float* Wo = (const float*)d_in[4];
    const float* bo = (const float*)d_in[5];
    float* out = (float*)d_out;

    cudaFuncSetAttribute(qkv_hmma_kernel, cudaFuncAttributeMaxDynamicSharedMemorySize, GEMM_SMEM);
    cudaFuncSetAttribute(out_hmma_kernel, cudaFuncAttributeMaxDynamicSharedMemorySize, GEMM_SMEM);
    cudaFuncSetAttribute(attn_hmma_kernel, cudaFuncAttributeMaxDynamicSharedMemorySize, ATTN_SMEM);

    // 1) fp32 -> fp16 conversions
    {
        const int nx = M_ROWS * K_DIM / 4;
        conv_x_kernel<<<(nx + 255) / 256, 256>>>(x);
        const int nw = N_DIM * K_DIM / 4;
        conv_w_kernel<<<dim3((nw + 255) / 256, 1, 4), 256>>>(Wq, Wk, Wv, Wo);
    }

    // 2) QKV projections; Q pre-scaled by log2e/8 in epilogue
    qkv_hmma_kernel<<<dim3(N_DIM / GBN, M_ROWS / GBM, 3), 256, GEMM_SMEM>>>();

    // 3) attention (f16x2 exp2, ones-column row sums, 2 CTAs/SM)
    attn_hmma_kernel<<<dim3(8, 64), 256, ATTN_SMEM>>>();

    // 4) output projection + bias
    out_hmma_kernel<<<dim3(N_DIM / GBN, M_ROWS / GBM), 256, GEMM_SMEM>>>(bo, out);
}